// round 1
// baseline (speedup 1.0000x reference)
#include <cuda_runtime.h>
#include <cuda_bf16.h>
#include <stdint.h>

#define NPTS 262144
#define DIM 512
#define NLBL 200
#define KNEG 8
#define EPSF 1e-7f
#define NEG_TH 0.85f
#define IGNORE_LBL 255

constexpr int BLOCKS   = 152;          // GB300 has 152 SMs; 1 CTA/SM (smem-limited)
constexpr int NTHREADS = 1024;
constexpr int NWARPS   = NTHREADS / 32;
constexpr int TOTWARPS = BLOCKS * NWARPS;

// dynamic smem layout
constexpr int SM_ANC_BYTES = NLBL * DIM * 2;        // 204800 B of bf16 anchors
constexpr int SM_A2_OFF    = SM_ANC_BYTES;          // 200 floats (padded to 256)
constexpr int SM_RED_OFF   = SM_A2_OFF + 256 * 4;   // 2*NWARPS floats
constexpr int SMEM_BYTES   = SM_RED_OFF + 2 * NWARPS * 4;

__device__ __nv_bfloat16 g_anc[NLBL * DIM];
__device__ float g_a2[NLBL];
__device__ int   g_is64;                 // bit0: labels are int64, bit1: neg_inds are int64
__device__ float g_ppos[BLOCKS];
__device__ float g_pneg[BLOCKS];

// ---------------------------------------------------------------------------
// Detect whether labels / neg_inds are int64 or int32.
// Values are nonneg and < 200, so for int64 (little-endian) every odd int32
// word is zero. For int32 data, 64 consecutive odd words all being zero has
// probability ~(1/200)^64 ~ 0.
// ---------------------------------------------------------------------------
__global__ void sniff_kernel(const int* __restrict__ labels,
                             const int* __restrict__ negs) {
    if (threadIdx.x == 0) {
        int f = 0;
        int ok = 1;
        for (int i = 0; i < 64; i++) if (labels[2 * i + 1] != 0) { ok = 0; break; }
        if (ok) f |= 1;
        ok = 1;
        for (int i = 0; i < 64; i++) if (negs[2 * i + 1] != 0) { ok = 0; break; }
        if (ok) f |= 2;
        g_is64 = f;
    }
}

// ---------------------------------------------------------------------------
// Convert anchor table fp32 -> bf16 and compute a2 = ||anchor_q||^2 from the
// QUANTIZED values (consistency keeps d2 = |f - a_q|^2 structure).
// ---------------------------------------------------------------------------
__global__ void convert_kernel(const float* __restrict__ anchors) {
    __shared__ float red[256];
    const int b = blockIdx.x;
    const int t = threadIdx.x;
    float acc = 0.f;
#pragma unroll
    for (int k = 0; k < 2; k++) {
        int e = t + 256 * k;
        float v = anchors[b * DIM + e];
        __nv_bfloat16 h = __float2bfloat16(v);
        g_anc[b * DIM + e] = h;
        float vq = __bfloat162float(h);
        acc = fmaf(vq, vq, acc);
    }
    red[t] = acc;
    __syncthreads();
    for (int s = 128; s > 0; s >>= 1) {
        if (t < s) red[t] += red[t + s];
        __syncthreads();
    }
    if (t == 0) g_a2[b] = red[0];
}

__device__ __forceinline__ float dotc(uint2 q, float4 f) {
    __nv_bfloat162 b0 = *reinterpret_cast<const __nv_bfloat162*>(&q.x);
    __nv_bfloat162 b1 = *reinterpret_cast<const __nv_bfloat162*>(&q.y);
    float2 a0 = __bfloat1622float2(b0);
    float2 a1 = __bfloat1622float2(b1);
    float s = f.x * a0.x;
    s = fmaf(f.y, a0.y, s);
    s = fmaf(f.z, a1.x, s);
    s = fmaf(f.w, a1.y, s);
    return s;
}

// ---------------------------------------------------------------------------
// Main kernel: persistent CTAs, whole anchor table (bf16) in shared memory.
// One warp per point; lane L owns feature elements {4L + 128c, c=0..3}:
//   - feature loads: 4x LDG.128, warp-contiguous (perfect coalescing)
//   - anchor loads : 4x LDS.64 per anchor, warp-contiguous (conflict-free)
// ---------------------------------------------------------------------------
__global__ __launch_bounds__(NTHREADS, 1)
void loss_kernel(const float* __restrict__ feats,
                 const void*  __restrict__ labels_v,
                 const void*  __restrict__ negs_v,
                 float* __restrict__ out,
                 int writeArrays) {
    extern __shared__ unsigned char smem[];
    __nv_bfloat16* sAnc = reinterpret_cast<__nv_bfloat16*>(smem);
    float* sA2  = reinterpret_cast<float*>(smem + SM_A2_OFF);
    float* sRed = reinterpret_cast<float*>(smem + SM_RED_OFF);

    // Stage anchors + a2 into shared memory.
    {
        const uint4* src = reinterpret_cast<const uint4*>(g_anc);
        uint4* dst = reinterpret_cast<uint4*>(smem);
        const int n16 = SM_ANC_BYTES / 16;
        for (int i = threadIdx.x; i < n16; i += NTHREADS) dst[i] = src[i];
        for (int i = threadIdx.x; i < NLBL; i += NTHREADS) sA2[i] = g_a2[i];
    }
    const int flags = g_is64;
    __syncthreads();
    const bool l64 = (flags & 1) != 0;
    const bool n64 = (flags & 2) != 0;

    const int warpId = threadIdx.x >> 5;
    const int lane   = threadIdx.x & 31;

    float sumPos = 0.f, sumNeg = 0.f;

    for (int p = blockIdx.x * NWARPS + warpId; p < NPTS; p += TOTWARPS) {
        // indices
        int lbl = l64 ? (int)reinterpret_cast<const long long*>(labels_v)[p]
                      : reinterpret_cast<const int*>(labels_v)[p];
        int myneg = 0;
        if (lane < KNEG) {
            myneg = n64 ? (int)reinterpret_cast<const long long*>(negs_v)[(size_t)p * KNEG + lane]
                        : reinterpret_cast<const int*>(negs_v)[(size_t)p * KNEG + lane];
        }
        int aidx[9];
        aidx[0] = lbl;
#pragma unroll
        for (int k = 0; k < KNEG; k++)
            aidx[k + 1] = __shfl_sync(0xffffffffu, myneg, k);

        // feature row (coalesced float4 loads)
        const float4* f4 = reinterpret_cast<const float4*>(feats + (size_t)p * DIM);
        float4 f0 = f4[lane];
        float4 f1 = f4[lane + 32];
        float4 f2v = f4[lane + 64];
        float4 f3 = f4[lane + 96];

        float f2a = f0.x * f0.x;
        f2a = fmaf(f0.y, f0.y, f2a);  f2a = fmaf(f0.z, f0.z, f2a);  f2a = fmaf(f0.w, f0.w, f2a);
        f2a = fmaf(f1.x, f1.x, f2a);  f2a = fmaf(f1.y, f1.y, f2a);  f2a = fmaf(f1.z, f1.z, f2a);  f2a = fmaf(f1.w, f1.w, f2a);
        f2a = fmaf(f2v.x, f2v.x, f2a); f2a = fmaf(f2v.y, f2v.y, f2a); f2a = fmaf(f2v.z, f2v.z, f2a); f2a = fmaf(f2v.w, f2v.w, f2a);
        f2a = fmaf(f3.x, f3.x, f2a);  f2a = fmaf(f3.y, f3.y, f2a);  f2a = fmaf(f3.z, f3.z, f2a);  f2a = fmaf(f3.w, f3.w, f2a);

        float acc[9];
#pragma unroll
        for (int k = 0; k < 9; k++) {
            const uint2* rp = reinterpret_cast<const uint2*>(sAnc + aidx[k] * DIM);
            uint2 q0 = rp[lane];
            uint2 q1 = rp[lane + 32];
            uint2 q2 = rp[lane + 64];
            uint2 q3 = rp[lane + 96];
            acc[k] = dotc(q0, f0) + dotc(q1, f1) + dotc(q2, f2v) + dotc(q3, f3);
        }

        // warp tree reduction (deterministic)
#pragma unroll
        for (int off = 16; off > 0; off >>= 1) {
            f2a += __shfl_down_sync(0xffffffffu, f2a, off);
#pragma unroll
            for (int k = 0; k < 9; k++)
                acc[k] += __shfl_down_sync(0xffffffffu, acc[k], off);
        }

        if (lane == 0) {
            float pd2  = f2a - 2.f * acc[0] + sA2[aidx[0]];
            float posd = sqrtf(fmaxf(pd2, 0.f) + EPSF);
            float nsum = 0.f;
#pragma unroll
            for (int k = 1; k < 9; k++) {
                float nd2 = f2a - 2.f * acc[k] + sA2[aidx[k]];
                nsum += sqrtf(fmaxf(nd2, 0.f) + EPSF);
            }
            bool  valid = (lbl != IGNORE_LBL);
            float pl = valid ? fmaxf(posd, 0.f) : 0.f;               // POS_THRESH = 0
            float nl = valid ? fmaxf(NEG_TH - nsum * 0.125f, 0.f) : 0.f;
            if (writeArrays) {
                out[1 + p]        = pl;
                out[1 + NPTS + p] = nl;
            }
            sumPos += pl;
            sumNeg += nl;
        }
    }

    if (lane == 0) {
        sRed[warpId]          = sumPos;
        sRed[NWARPS + warpId] = sumNeg;
    }
    __syncthreads();
    if (threadIdx.x < 32) {
        float sp = sRed[threadIdx.x];
        float sn = sRed[NWARPS + threadIdx.x];
#pragma unroll
        for (int off = 16; off > 0; off >>= 1) {
            sp += __shfl_down_sync(0xffffffffu, sp, off);
            sn += __shfl_down_sync(0xffffffffu, sn, off);
        }
        if (threadIdx.x == 0) {
            g_ppos[blockIdx.x] = sp;
            g_pneg[blockIdx.x] = sn;
        }
    }
}

// Deterministic final reduction over block partials.
__global__ void final_kernel(float* __restrict__ out) {
    __shared__ float sp[256];
    __shared__ float sn[256];
    const int t = threadIdx.x;
    sp[t] = (t < BLOCKS) ? g_ppos[t] : 0.f;
    sn[t] = (t < BLOCKS) ? g_pneg[t] : 0.f;
    __syncthreads();
    for (int s = 128; s > 0; s >>= 1) {
        if (t < s) { sp[t] += sp[t + s]; sn[t] += sn[t + s]; }
        __syncthreads();
    }
    if (t == 0) out[0] = (sp[0] + sn[0]) * (1.0f / (float)NPTS);
}

extern "C" void kernel_launch(void* const* d_in, const int* in_sizes, int n_in,
                              void* d_out, int out_size) {
    const float* feats   = (const float*)d_in[0];
    const void*  labels  = d_in[1];
    const float* anchors = (const float*)d_in[2];
    const void*  negs    = d_in[3];
    float* out = (float*)d_out;

    const int writeArrays = (out_size >= 1 + 2 * NPTS) ? 1 : 0;

    cudaFuncSetAttribute(loss_kernel, cudaFuncAttributeMaxDynamicSharedMemorySize, SMEM_BYTES);

    sniff_kernel<<<1, 32>>>((const int*)labels, (const int*)negs);
    convert_kernel<<<NLBL, 256>>>(anchors);
    loss_kernel<<<BLOCKS, NTHREADS, SMEM_BYTES>>>(feats, labels, negs, out, writeArrays);
    final_kernel<<<1, 256>>>(out);
}

// round 2
// speedup vs baseline: 1.1377x; 1.1377x over previous
#include <cuda_runtime.h>
#include <cuda_bf16.h>
#include <stdint.h>

#define NPTS 262144
#define DIM 512
#define NLBL 200
#define KNEG 8
#define EPSF 1e-7f
#define NEG_TH 0.85f
#define IGNORE_LBL 255

constexpr int BLOCKS   = 152;
constexpr int NTHREADS = 1024;
constexpr int NWARPS   = NTHREADS / 32;
constexpr int TOTWARPS = BLOCKS * NWARPS;

constexpr int SM_ANC_BYTES = NLBL * DIM * 2;        // 204800 B bf16 anchors
constexpr int SM_A2_OFF    = SM_ANC_BYTES;
constexpr int SM_RED_OFF   = SM_A2_OFF + 256 * 4;
constexpr int SMEM_BYTES   = SM_RED_OFF + 2 * NWARPS * 4;

__device__ __nv_bfloat16 g_anc[NLBL * DIM];
__device__ float g_a2[NLBL];
__device__ int   g_is64;
__device__ float g_ppos[BLOCKS];
__device__ float g_pneg[BLOCKS];

// ---------------------------------------------------------------------------
// int64-vs-int32 sniff (values nonneg < 200 -> odd words zero iff int64)
// ---------------------------------------------------------------------------
__global__ void sniff_kernel(const int* __restrict__ labels,
                             const int* __restrict__ negs) {
    if (threadIdx.x == 0) {
        int f = 0, ok = 1;
        for (int i = 0; i < 64; i++) if (labels[2 * i + 1] != 0) { ok = 0; break; }
        if (ok) f |= 1;
        ok = 1;
        for (int i = 0; i < 64; i++) if (negs[2 * i + 1] != 0) { ok = 0; break; }
        if (ok) f |= 2;
        g_is64 = f;
    }
}

// fp32 anchors -> bf16 + a2 = ||quantized anchor||^2
__global__ void convert_kernel(const float* __restrict__ anchors) {
    __shared__ float red[256];
    const int b = blockIdx.x;
    const int t = threadIdx.x;
    float acc = 0.f;
#pragma unroll
    for (int k = 0; k < 2; k++) {
        int e = t + 256 * k;
        float v = anchors[b * DIM + e];
        __nv_bfloat16 h = __float2bfloat16(v);
        g_anc[b * DIM + e] = h;
        float vq = __bfloat162float(h);
        acc = fmaf(vq, vq, acc);
    }
    red[t] = acc;
    __syncthreads();
    for (int s = 128; s > 0; s >>= 1) {
        if (t < s) red[t] += red[t + s];
        __syncthreads();
    }
    if (t == 0) g_a2[b] = red[0];
}

// ---------------------------------------------------------------------------
// f32x2 helpers: Blackwell packed fp32 FMA + bf16x2 -> f32x2 via ALU bit ops
// ---------------------------------------------------------------------------
__device__ __forceinline__ unsigned long long cvt2(unsigned int w) {
    // bf16x2 word [h1:h0] -> packed f32x2 {f(h0), f(h1)} using shl/and (ALU pipe)
    unsigned long long r;
    asm("{ .reg .b32 lo, hi;\n"
        "  shl.b32 lo, %1, 16;\n"
        "  and.b32 hi, %1, 0xFFFF0000;\n"
        "  mov.b64 %0, {lo, hi}; }" : "=l"(r) : "r"(w));
    return r;
}
__device__ __forceinline__ void fma2(unsigned long long& acc,
                                     unsigned long long a,
                                     unsigned long long b) {
    asm("fma.rn.f32x2 %0, %1, %2, %0;" : "+l"(acc) : "l"(a), "l"(b));
}
__device__ __forceinline__ float hadd2(unsigned long long a) {
    float lo, hi;
    asm("mov.b64 {%0, %1}, %2;" : "=f"(lo), "=f"(hi) : "l"(a));
    return lo + hi;
}
__device__ __forceinline__ unsigned long long pk2(float x, float y) {
    unsigned long long r;
    asm("mov.b64 %0, {%1, %2};" : "=l"(r) : "f"(x), "f"(y));
    return r;
}

// ---------------------------------------------------------------------------
// Main kernel: persistent CTAs, bf16 anchor table in smem, warp-per-point.
// Lane L owns feature/anchor elements {4L+128c, c=0..3}.
// ---------------------------------------------------------------------------
__global__ __launch_bounds__(NTHREADS, 1)
void loss_kernel(const float* __restrict__ feats,
                 const void*  __restrict__ labels_v,
                 const void*  __restrict__ negs_v,
                 float* __restrict__ out,
                 int writeArrays) {
    extern __shared__ unsigned char smem[];
    __nv_bfloat16* sAnc = reinterpret_cast<__nv_bfloat16*>(smem);
    float* sA2  = reinterpret_cast<float*>(smem + SM_A2_OFF);
    float* sRed = reinterpret_cast<float*>(smem + SM_RED_OFF);

    {
        const uint4* src = reinterpret_cast<const uint4*>(g_anc);
        uint4* dst = reinterpret_cast<uint4*>(smem);
        const int n16 = SM_ANC_BYTES / 16;
        for (int i = threadIdx.x; i < n16; i += NTHREADS) dst[i] = src[i];
        for (int i = threadIdx.x; i < NLBL; i += NTHREADS) sA2[i] = g_a2[i];
    }
    const int flags = g_is64;
    __syncthreads();
    const bool l64 = (flags & 1) != 0;
    const bool n64 = (flags & 2) != 0;

    const int warpId = threadIdx.x >> 5;
    const int lane   = threadIdx.x & 31;

    float sumPos = 0.f, sumNeg = 0.f;

    for (int p = blockIdx.x * NWARPS + warpId; p < NPTS; p += TOTWARPS) {
        // issue feature loads first (max MLP)
        const float4* f4 = reinterpret_cast<const float4*>(feats + (size_t)p * DIM);
        float4 f0 = f4[lane];
        float4 f1 = f4[lane + 32];
        float4 f2v = f4[lane + 64];
        float4 f3 = f4[lane + 96];

        int lbl = l64 ? (int)reinterpret_cast<const long long*>(labels_v)[p]
                      : reinterpret_cast<const int*>(labels_v)[p];
        int myneg = 0;
        if (lane < KNEG) {
            myneg = n64 ? (int)reinterpret_cast<const long long*>(negs_v)[(size_t)p * KNEG + lane]
                        : reinterpret_cast<const int*>(negs_v)[(size_t)p * KNEG + lane];
        }
        int aidx[9];
        aidx[0] = lbl;
#pragma unroll
        for (int k = 0; k < KNEG; k++)
            aidx[k + 1] = __shfl_sync(0xffffffffu, myneg, k);

        // pack features into f32x2 pairs
        unsigned long long fp[8];
        fp[0] = pk2(f0.x, f0.y);  fp[1] = pk2(f0.z, f0.w);
        fp[2] = pk2(f1.x, f1.y);  fp[3] = pk2(f1.z, f1.w);
        fp[4] = pk2(f2v.x, f2v.y); fp[5] = pk2(f2v.z, f2v.w);
        fp[6] = pk2(f3.x, f3.y);  fp[7] = pk2(f3.z, f3.w);

        // ||f||^2 (packed)
        unsigned long long nacc = 0ull;
#pragma unroll
        for (int j = 0; j < 8; j++) fma2(nacc, fp[j], fp[j]);
        float f2a = hadd2(nacc);

        // 9 anchor dot products: 8 FFMA2 + 16 ALU cvt ops per anchor
        float dots[9];
#pragma unroll
        for (int k = 0; k < 9; k++) {
            const uint2* rp = reinterpret_cast<const uint2*>(sAnc + aidx[k] * DIM);
            uint2 q0 = rp[lane];
            uint2 q1 = rp[lane + 32];
            uint2 q2 = rp[lane + 64];
            uint2 q3 = rp[lane + 96];
            unsigned long long acc = 0ull;
            fma2(acc, cvt2(q0.x), fp[0]);
            fma2(acc, cvt2(q0.y), fp[1]);
            fma2(acc, cvt2(q1.x), fp[2]);
            fma2(acc, cvt2(q1.y), fp[3]);
            fma2(acc, cvt2(q2.x), fp[4]);
            fma2(acc, cvt2(q2.y), fp[5]);
            fma2(acc, cvt2(q3.x), fp[6]);
            fma2(acc, cvt2(q3.y), fp[7]);
            dots[k] = hadd2(acc);
        }

        // warp tree reduction (deterministic)
#pragma unroll
        for (int off = 16; off > 0; off >>= 1) {
            f2a += __shfl_down_sync(0xffffffffu, f2a, off);
#pragma unroll
            for (int k = 0; k < 9; k++)
                dots[k] += __shfl_down_sync(0xffffffffu, dots[k], off);
        }

        if (lane == 0) {
            float pd2  = f2a - 2.f * dots[0] + sA2[aidx[0]];
            float posd = sqrtf(fmaxf(pd2, 0.f) + EPSF);
            float nsum = 0.f;
#pragma unroll
            for (int k = 1; k < 9; k++) {
                float nd2 = f2a - 2.f * dots[k] + sA2[aidx[k]];
                nsum += sqrtf(fmaxf(nd2, 0.f) + EPSF);
            }
            bool  valid = (lbl != IGNORE_LBL);
            float pl = valid ? fmaxf(posd, 0.f) : 0.f;
            float nl = valid ? fmaxf(NEG_TH - nsum * 0.125f, 0.f) : 0.f;
            if (writeArrays) {
                out[1 + p]        = pl;
                out[1 + NPTS + p] = nl;
            }
            sumPos += pl;
            sumNeg += nl;
        }
    }

    if (lane == 0) {
        sRed[warpId]          = sumPos;
        sRed[NWARPS + warpId] = sumNeg;
    }
    __syncthreads();
    if (threadIdx.x < 32) {
        float sp = sRed[threadIdx.x];
        float sn = sRed[NWARPS + threadIdx.x];
#pragma unroll
        for (int off = 16; off > 0; off >>= 1) {
            sp += __shfl_down_sync(0xffffffffu, sp, off);
            sn += __shfl_down_sync(0xffffffffu, sn, off);
        }
        if (threadIdx.x == 0) {
            g_ppos[blockIdx.x] = sp;
            g_pneg[blockIdx.x] = sn;
        }
    }
}

__global__ void final_kernel(float* __restrict__ out) {
    __shared__ float sp[256];
    __shared__ float sn[256];
    const int t = threadIdx.x;
    sp[t] = (t < BLOCKS) ? g_ppos[t] : 0.f;
    sn[t] = (t < BLOCKS) ? g_pneg[t] : 0.f;
    __syncthreads();
    for (int s = 128; s > 0; s >>= 1) {
        if (t < s) { sp[t] += sp[t + s]; sn[t] += sn[t + s]; }
        __syncthreads();
    }
    if (t == 0) out[0] = (sp[0] + sn[0]) * (1.0f / (float)NPTS);
}

extern "C" void kernel_launch(void* const* d_in, const int* in_sizes, int n_in,
                              void* d_out, int out_size) {
    const float* feats   = (const float*)d_in[0];
    const void*  labels  = d_in[1];
    const float* anchors = (const float*)d_in[2];
    const void*  negs    = d_in[3];
    float* out = (float*)d_out;

    const int writeArrays = (out_size >= 1 + 2 * NPTS) ? 1 : 0;

    cudaFuncSetAttribute(loss_kernel, cudaFuncAttributeMaxDynamicSharedMemorySize, SMEM_BYTES);

    sniff_kernel<<<1, 32>>>((const int*)labels, (const int*)negs);
    convert_kernel<<<NLBL, 256>>>(anchors);
    loss_kernel<<<BLOCKS, NTHREADS, SMEM_BYTES>>>(feats, labels, negs, out, writeArrays);
    final_kernel<<<1, 256>>>(out);
}

// round 4
// speedup vs baseline: 1.2173x; 1.0700x over previous
#include <cuda_runtime.h>
#include <cuda_fp16.h>
#include <stdint.h>

#define NPTS 262144
#define DIM 512
#define NLBL 200
#define KNEG 8
#define EPSF 1e-7f
#define NEG_TH 0.85f
#define IGNORE_LBL 255

constexpr int BLOCKS   = 152;
constexpr int NTHREADS = 1024;
constexpr int NWARPS   = NTHREADS / 32;
constexpr int TOTWARPS = BLOCKS * NWARPS;

constexpr int SM_ANC_BYTES = NLBL * DIM * 2;        // 204800 B fp16 anchors
constexpr int SM_A2_OFF    = SM_ANC_BYTES;          // 256 floats
constexpr int SM_RED_OFF   = SM_A2_OFF + 256 * 4;
constexpr int SMEM_BYTES   = SM_RED_OFF + 2 * NWARPS * 4;

__device__ float g_ppos[BLOCKS];
__device__ float g_pneg[BLOCKS];
__device__ unsigned int g_count = 0;

// ---------------------------------------------------------------------------
// helpers
// ---------------------------------------------------------------------------
__device__ __forceinline__ unsigned cvt_f16x2(float hi, float lo) {
    unsigned r;
    asm("cvt.rn.f16x2.f32 %0, %1, %2;" : "=r"(r) : "f"(hi), "f"(lo));
    return r;
}
__device__ __forceinline__ void hfma2(unsigned& acc, unsigned a, unsigned b) {
    asm("fma.rn.f16x2 %0, %1, %2, %0;" : "+r"(acc) : "r"(a), "r"(b));
}
__device__ __forceinline__ unsigned hadd2(unsigned a, unsigned b) {
    unsigned r;
    asm("add.rn.f16x2 %0, %1, %2;" : "=r"(r) : "r"(a), "r"(b));
    return r;
}
__device__ __forceinline__ unsigned prmt(unsigned a, unsigned b, unsigned sel) {
    unsigned r;
    asm("prmt.b32 %0, %1, %2, %3;" : "=r"(r) : "r"(a), "r"(b), "r"(sel));
    return r;
}
// combine two f16x2 accumulators -> {loA+hiA, loB+hiB}
__device__ __forceinline__ unsigned pairsum(unsigned a, unsigned b) {
    unsigned lo = prmt(a, b, 0x5410u);   // {a.lo, b.lo}
    unsigned hi = prmt(a, b, 0x7632u);   // {a.hi, b.hi}
    return hadd2(lo, hi);
}
__device__ __forceinline__ float sqrt_approx(float x) {
    float r;
    asm("sqrt.approx.f32 %0, %1;" : "=f"(r) : "f"(x));
    return r;
}
__device__ __forceinline__ float wred(float v) {          // 5-step bfly sum
#pragma unroll
    for (int off = 16; off > 0; off >>= 1)
        v += __shfl_xor_sync(0xffffffffu, v, off);
    return v;
}

// ---------------------------------------------------------------------------
// Single fused kernel.
// ---------------------------------------------------------------------------
__global__ __launch_bounds__(NTHREADS, 1)
void loss_kernel(const float* __restrict__ feats,
                 const void*  __restrict__ labels_v,
                 const float* __restrict__ anchors,
                 const void*  __restrict__ negs_v,
                 float* __restrict__ out,
                 int writeArrays) {
    extern __shared__ unsigned char smem[];
    char*  sAncB = reinterpret_cast<char*>(smem);
    float* sA2   = reinterpret_cast<float*>(smem + SM_A2_OFF);
    float* sRed  = reinterpret_cast<float*>(smem + SM_RED_OFF);
    __shared__ int sFlags;
    __shared__ int sIsLast;

    const int warpId = threadIdx.x >> 5;
    const int lane   = threadIdx.x & 31;

    // ---- dtype sniff: values nonneg < 200 -> odd int32 words zero iff int64
    if (warpId == 0) {
        const int* li = reinterpret_cast<const int*>(labels_v);
        const int* ni = reinterpret_cast<const int*>(negs_v);
        int lnz = li[2 * lane + 1] | li[2 * lane + 65];
        int nnz = ni[2 * lane + 1] | ni[2 * lane + 65];
        unsigned lb = __ballot_sync(0xffffffffu, lnz != 0);
        unsigned nb = __ballot_sync(0xffffffffu, nnz != 0);
        if (lane == 0) sFlags = ((lb == 0u) ? 1 : 0) | ((nb == 0u) ? 2 : 0);
    }

    // ---- stage anchors fp32 -> fp16 smem (permuted layout) + a2
    // Lane L's 16 bytes of row r (sweep s) hold elements {4L+128c .. +3} for
    // c = 2s, 2s+1, matching the main-loop feature register layout.
    for (int r = warpId; r < NLBL; r += NWARPS) {
        const float4* src = reinterpret_cast<const float4*>(anchors + r * DIM);
        unsigned p[8];
        float a2p = 0.f;
#pragma unroll
        for (int c = 0; c < 4; c++) {
            float4 v = src[lane + 32 * c];
            unsigned w0 = cvt_f16x2(v.y, v.x);
            unsigned w1 = cvt_f16x2(v.w, v.z);
            p[2 * c]     = w0;
            p[2 * c + 1] = w1;
            __half2 h0 = *reinterpret_cast<__half2*>(&w0);
            __half2 h1 = *reinterpret_cast<__half2*>(&w1);
            float2 q0 = __half22float2(h0);
            float2 q1 = __half22float2(h1);
            a2p = fmaf(q0.x, q0.x, a2p); a2p = fmaf(q0.y, q0.y, a2p);
            a2p = fmaf(q1.x, q1.x, a2p); a2p = fmaf(q1.y, q1.y, a2p);
        }
        uint4* dst = reinterpret_cast<uint4*>(sAncB + (size_t)r * 1024);
        dst[lane]      = make_uint4(p[0], p[1], p[2], p[3]);
        dst[lane + 32] = make_uint4(p[4], p[5], p[6], p[7]);
        float a2 = wred(a2p);
        if (lane == 0) sA2[r] = a2;
    }
    __syncthreads();

    const bool l64 = (sFlags & 1) != 0;
    const bool n64 = (sFlags & 2) != 0;

    float sumPos = 0.f, sumNeg = 0.f;

    for (int p = blockIdx.x * NWARPS + warpId; p < NPTS; p += TOTWARPS) {
        // features: 4 coalesced float4 loads; lane L owns elems {4L+128c}
        const float4* f4 = reinterpret_cast<const float4*>(feats + (size_t)p * DIM);
        float4 f0 = f4[lane];
        float4 f1 = f4[lane + 32];
        float4 f2v = f4[lane + 64];
        float4 f3 = f4[lane + 96];

        // indices: broadcast loads; every lane holds all 9 row indices
        int lbl = l64 ? (int)reinterpret_cast<const long long*>(labels_v)[p]
                      : reinterpret_cast<const int*>(labels_v)[p];
        int nv0, nv1, nv2, nv3, nv4, nv5, nv6, nv7;
        if (n64) {
            const uint4* np = reinterpret_cast<const uint4*>(
                (const char*)negs_v + (size_t)p * 64);
            uint4 a = np[0], b = np[1], c = np[2], d = np[3];
            nv0 = (int)a.x; nv1 = (int)a.z;
            nv2 = (int)b.x; nv3 = (int)b.z;
            nv4 = (int)c.x; nv5 = (int)c.z;
            nv6 = (int)d.x; nv7 = (int)d.z;
        } else {
            const uint4* np = reinterpret_cast<const uint4*>(
                (const char*)negs_v + (size_t)p * 32);
            uint4 a = np[0], b = np[1];
            nv0 = (int)a.x; nv1 = (int)a.y; nv2 = (int)a.z; nv3 = (int)a.w;
            nv4 = (int)b.x; nv5 = (int)b.y; nv6 = (int)b.z; nv7 = (int)b.w;
        }
        int aidx[9] = {lbl, nv0, nv1, nv2, nv3, nv4, nv5, nv6, nv7};

        // pack features to f16x2 (same lo/hi convention as staging)
        unsigned fp[8];
        fp[0] = cvt_f16x2(f0.y, f0.x);   fp[1] = cvt_f16x2(f0.w, f0.z);
        fp[2] = cvt_f16x2(f1.y, f1.x);   fp[3] = cvt_f16x2(f1.w, f1.z);
        fp[4] = cvt_f16x2(f2v.y, f2v.x); fp[5] = cvt_f16x2(f2v.w, f2v.z);
        fp[6] = cvt_f16x2(f3.y, f3.x);   fp[7] = cvt_f16x2(f3.w, f3.z);

        // ||f||^2 per-lane partial (fp32, exact features)
        float f2p = f0.x * f0.x;
        f2p = fmaf(f0.y, f0.y, f2p); f2p = fmaf(f0.z, f0.z, f2p); f2p = fmaf(f0.w, f0.w, f2p);
        f2p = fmaf(f1.x, f1.x, f2p); f2p = fmaf(f1.y, f1.y, f2p); f2p = fmaf(f1.z, f1.z, f2p); f2p = fmaf(f1.w, f1.w, f2p);
        f2p = fmaf(f2v.x, f2v.x, f2p); f2p = fmaf(f2v.y, f2v.y, f2p); f2p = fmaf(f2v.z, f2v.z, f2p); f2p = fmaf(f2v.w, f2v.w, f2p);
        f2p = fmaf(f3.x, f3.x, f2p); f2p = fmaf(f3.y, f3.y, f2p); f2p = fmaf(f3.z, f3.z, f2p); f2p = fmaf(f3.w, f3.w, f2p);

        // 9 dot products: 2 LDS.128 + 8 HFMA2 each, accum in f16x2
        unsigned acc[9];
#pragma unroll
        for (int k = 0; k < 9; k++) {
            const uint4* rp = reinterpret_cast<const uint4*>(
                sAncB + (size_t)aidx[k] * 1024);
            uint4 qa = rp[lane];
            uint4 qb = rp[lane + 32];
            unsigned a = 0u;
            hfma2(a, qa.x, fp[0]); hfma2(a, qa.y, fp[1]);
            hfma2(a, qa.z, fp[2]); hfma2(a, qa.w, fp[3]);
            hfma2(a, qb.x, fp[4]); hfma2(a, qb.y, fp[5]);
            hfma2(a, qb.z, fp[6]); hfma2(a, qb.w, fp[7]);
            acc[k] = a;
        }

        // pack 9 accumulators into 5 f16x2 regs: (d0,d1)(d2,d3)(d4,d5)(d6,d7)(d8,d8)
        unsigned pk[5];
        pk[0] = pairsum(acc[0], acc[1]);
        pk[1] = pairsum(acc[2], acc[3]);
        pk[2] = pairsum(acc[4], acc[5]);
        pk[3] = pairsum(acc[6], acc[7]);
        pk[4] = pairsum(acc[8], acc[8]);

        // butterfly reduction: 5 packed f16x2 + f2 (fp32)
#pragma unroll
        for (int off = 16; off > 0; off >>= 1) {
#pragma unroll
            for (int j = 0; j < 5; j++)
                pk[j] = hadd2(pk[j], __shfl_xor_sync(0xffffffffu, pk[j], off));
            f2p += __shfl_xor_sync(0xffffffffu, f2p, off);
        }

        // lane-parallel epilogue: lane k (0..8) handles anchor k
        const int k = lane;
        unsigned v = (k < 2) ? pk[0] : (k < 4) ? pk[1] : (k < 6) ? pk[2]
                   : (k < 8) ? pk[3] : pk[4];
        __half2 hv = *reinterpret_cast<__half2*>(&v);
        float dk = (k & 1) ? __half2float(hv.y) : __half2float(hv.x);
        int myIdx = (k >= 1 && k <= 8)
            ? ((k <= 4) ? ((k <= 2) ? (k == 1 ? nv0 : nv1) : (k == 3 ? nv2 : nv3))
                        : ((k <= 6) ? (k == 5 ? nv4 : nv5) : (k == 7 ? nv6 : nv7)))
            : lbl;
        float a2v = sA2[myIdx];
        float d2 = fmaf(-2.f, dk, f2p) + a2v;
        float dist = sqrt_approx(fmaxf(d2, 0.f) + EPSF);
        float nd = (k >= 1 && k <= 8) ? dist : 0.f;
        nd = wred(nd);                       // nsum in all lanes

        if (lane == 0) {
            bool  valid = (lbl != IGNORE_LBL);
            float pl = valid ? fmaxf(dist, 0.f) : 0.f;          // POS_THRESH=0
            float nl = valid ? fmaxf(NEG_TH - nd * 0.125f, 0.f) : 0.f;
            if (writeArrays) {
                out[1 + p]        = pl;
                out[1 + NPTS + p] = nl;
            }
            sumPos += pl;
            sumNeg += nl;
        }
    }

    // ---- block partials
    if (lane == 0) {
        sRed[warpId]          = sumPos;
        sRed[NWARPS + warpId] = sumNeg;
    }
    __syncthreads();
    if (threadIdx.x < 32) {
        float sp = wred(sRed[threadIdx.x]);
        float sn = wred(sRed[NWARPS + threadIdx.x]);
        if (threadIdx.x == 0) {
            g_ppos[blockIdx.x] = sp;
            g_pneg[blockIdx.x] = sn;
        }
    }

    // ---- last-block grid reduction
    if (threadIdx.x == 0) {
        __threadfence();
        unsigned int c = atomicAdd(&g_count, 1u);
        sIsLast = (c == (unsigned)(BLOCKS - 1)) ? 1 : 0;
    }
    __syncthreads();
    if (sIsLast) {
        __threadfence();
        float sp = 0.f, sn = 0.f;
        if (threadIdx.x < BLOCKS) {
            sp = g_ppos[threadIdx.x];
            sn = g_pneg[threadIdx.x];
        }
        if (warpId < 5) {
            sp = wred(sp);
            sn = wred(sn);
            if (lane == 0) { sRed[warpId] = sp; sRed[8 + warpId] = sn; }
        }
        __syncthreads();
        if (threadIdx.x == 0) {
            float tp = 0.f, tn = 0.f;
#pragma unroll
            for (int i = 0; i < 5; i++) { tp += sRed[i]; tn += sRed[8 + i]; }
            out[0] = (tp + tn) * (1.0f / (float)NPTS);
            atomicExch(&g_count, 0u);      // reset for next graph replay
        }
    }
}

extern "C" void kernel_launch(void* const* d_in, const int* in_sizes, int n_in,
                              void* d_out, int out_size) {
    const float* feats   = (const float*)d_in[0];
    const void*  labels  = d_in[1];
    const float* anchors = (const float*)d_in[2];
    const void*  negs    = d_in[3];
    float* out = (float*)d_out;

    const int writeArrays = (out_size >= 1 + 2 * NPTS) ? 1 : 0;

    cudaFuncSetAttribute(loss_kernel, cudaFuncAttributeMaxDynamicSharedMemorySize, SMEM_BYTES);
    loss_kernel<<<BLOCKS, NTHREADS, SMEM_BYTES>>>(feats, labels, anchors, negs, out, writeArrays);
}

// round 5
// speedup vs baseline: 1.5714x; 1.2909x over previous
#include <cuda_runtime.h>
#include <cuda_fp16.h>
#include <stdint.h>

#define NPTS 262144
#define DIM 512
#define NLBL 200
#define KNEG 8
#define EPSF 1e-7f
#define NEG_TH 0.85f
#define IGNORE_LBL 255

constexpr int BLOCKS   = 152;
constexpr int NTHREADS = 1024;
constexpr int NWARPS   = NTHREADS / 32;
constexpr int TOTWARPS = BLOCKS * NWARPS;

// dynamic smem layout: e5m2 neg anchor table + a2 tables + reduction scratch
constexpr int SM_NEG_BYTES = NLBL * DIM;            // 102400 B e5m2 anchors
constexpr int SM_A2P_OFF   = SM_NEG_BYTES;          // fp16-consistent a2 (pos)
constexpr int SM_A2N_OFF   = SM_A2P_OFF + 1024;     // e5m2-consistent a2 (neg)
constexpr int SM_RED_OFF   = SM_A2N_OFF + 1024;
constexpr int SMEM_BYTES   = SM_RED_OFF + 2 * NWARPS * 4;

// fp16 positive-anchor table in gmem (each CTA writes identical data, then
// reads its own writes after __syncthreads; duplicate writes are benign).
__device__ uint4 g_posU4[NLBL * 64];   // row r: chunk j(0,1) x lane: [r*64 + j*32 + lane]

__device__ float g_ppos[BLOCKS];
__device__ float g_pneg[BLOCKS];
__device__ unsigned int g_count = 0;

// ---------------------------------------------------------------------------
// helpers
// ---------------------------------------------------------------------------
__device__ __forceinline__ unsigned cvt_f16x2(float hi, float lo) {
    unsigned r;
    asm("cvt.rn.f16x2.f32 %0, %1, %2;" : "=r"(r) : "f"(hi), "f"(lo));
    return r;
}
__device__ __forceinline__ void hfma2(unsigned& acc, unsigned a, unsigned b) {
    asm("fma.rn.f16x2 %0, %1, %2, %0;" : "+r"(acc) : "r"(a), "r"(b));
}
__device__ __forceinline__ unsigned hfma3(unsigned a, unsigned b, unsigned c) {
    unsigned r;
    asm("fma.rn.f16x2 %0, %1, %2, %3;" : "=r"(r) : "r"(a), "r"(b), "r"(c));
    return r;
}
__device__ __forceinline__ unsigned hadd2(unsigned a, unsigned b) {
    unsigned r;
    asm("add.rn.f16x2 %0, %1, %2;" : "=r"(r) : "r"(a), "r"(b));
    return r;
}
__device__ __forceinline__ unsigned prmt(unsigned a, unsigned b, unsigned sel) {
    unsigned r;
    asm("prmt.b32 %0, %1, %2, %3;" : "=r"(r) : "r"(a), "r"(b), "r"(sel));
    return r;
}
__device__ __forceinline__ unsigned prmt0(unsigned a, unsigned sel) {
    unsigned r;
    asm("prmt.b32 %0, %1, %2, %3;" : "=r"(r) : "r"(a), "r"(0u), "r"(sel));
    return r;
}
// {aLo+aHi, bLo+bHi}
__device__ __forceinline__ unsigned pairsum(unsigned a, unsigned b) {
    return hadd2(prmt(a, b, 0x5410u), prmt(a, b, 0x7632u));
}
__device__ __forceinline__ float sqrt_approx(float x) {
    float r;
    asm("sqrt.approx.f32 %0, %1;" : "=f"(r) : "f"(x));
    return r;
}
__device__ __forceinline__ float wred(float v) {
#pragma unroll
    for (int off = 16; off > 0; off >>= 1)
        v += __shfl_xor_sync(0xffffffffu, v, off);
    return v;
}

// ---------------------------------------------------------------------------
// Single fused kernel.
// ---------------------------------------------------------------------------
__global__ __launch_bounds__(NTHREADS, 1)
void loss_kernel(const float* __restrict__ feats,
                 const void*  __restrict__ labels_v,
                 const float* __restrict__ anchors,
                 const void*  __restrict__ negs_v,
                 float* __restrict__ out,
                 int writeArrays) {
    extern __shared__ unsigned char smem[];
    unsigned char* sNegB = smem;
    float* sA2p = reinterpret_cast<float*>(smem + SM_A2P_OFF);
    float* sA2n = reinterpret_cast<float*>(smem + SM_A2N_OFF);
    float* sRed = reinterpret_cast<float*>(smem + SM_RED_OFF);
    __shared__ int sFlags;
    __shared__ int sIsLast;

    const int warpId = threadIdx.x >> 5;
    const int lane   = threadIdx.x & 31;

    // ---- dtype sniff: values nonneg < 200 -> odd int32 words zero iff int64
    if (warpId == 0) {
        const int* li = reinterpret_cast<const int*>(labels_v);
        const int* ni = reinterpret_cast<const int*>(negs_v);
        int lnz = li[2 * lane + 1] | li[2 * lane + 65];
        int nnz = ni[2 * lane + 1] | ni[2 * lane + 65];
        unsigned lb = __ballot_sync(0xffffffffu, lnz != 0);
        unsigned nb = __ballot_sync(0xffffffffu, nnz != 0);
        if (lane == 0) sFlags = ((lb == 0u) ? 1 : 0) | ((nb == 0u) ? 2 : 0);
    }

    // ---- stage anchors: fp32 -> fp16 (gmem table, pos) + e5m2 (smem, negs)
    // Lane L owns elements {4L+128c .. +3}, c = 0..3 (matches main loop).
    for (int r = warpId; r < NLBL; r += NWARPS) {
        const float4* src = reinterpret_cast<const float4*>(anchors + r * DIM);
        unsigned w[8];
        float a2p = 0.f, a2n = 0.f;
#pragma unroll
        for (int c = 0; c < 4; c++) {
            float4 v = src[lane + 32 * c];
            w[2 * c]     = cvt_f16x2(v.y, v.x);
            w[2 * c + 1] = cvt_f16x2(v.w, v.z);
        }
        // fp16-consistent a2 (positive path)
#pragma unroll
        for (int j = 0; j < 8; j++) {
            __half2 h = *reinterpret_cast<__half2*>(&w[j]);
            float2 q = __half22float2(h);
            a2p = fmaf(q.x, q.x, a2p);
            a2p = fmaf(q.y, q.y, a2p);
        }
        // e5m2 bytes: round f16 mantissa byte then take high bytes
        unsigned b[4];
#pragma unroll
        for (int c = 0; c < 4; c++) {
            unsigned r0 = w[2 * c] + 0x00800080u;
            unsigned r1 = w[2 * c + 1] + 0x00800080u;
            b[c] = prmt(r0, r1, 0x7531u);
            // e5m2-consistent a2 (reconstruct exactly like the main loop)
            unsigned plo = prmt0(b[c], 0x1404u);
            unsigned phi = prmt0(b[c], 0x3424u);
            __half2 hlo = *reinterpret_cast<__half2*>(&plo);
            __half2 hhi = *reinterpret_cast<__half2*>(&phi);
            float2 qlo = __half22float2(hlo);
            float2 qhi = __half22float2(hhi);
            a2n = fmaf(qlo.x, qlo.x, a2n); a2n = fmaf(qlo.y, qlo.y, a2n);
            a2n = fmaf(qhi.x, qhi.x, a2n); a2n = fmaf(qhi.y, qhi.y, a2n);
        }
        reinterpret_cast<uint4*>(sNegB + r * 512)[lane] = make_uint4(b[0], b[1], b[2], b[3]);
        g_posU4[r * 64 + lane]      = make_uint4(w[0], w[1], w[2], w[3]);
        g_posU4[r * 64 + 32 + lane] = make_uint4(w[4], w[5], w[6], w[7]);
        float s2p = wred(a2p);
        float s2n = wred(a2n);
        if (lane == 0) { sA2p[r] = s2p; sA2n[r] = s2n; }
    }
    __syncthreads();   // orders own-CTA g_posU4 stores before loads, + smem

    const bool l64 = (sFlags & 1) != 0;
    const bool n64 = (sFlags & 2) != 0;

    float sumPos = 0.f, sumNeg = 0.f;

    for (int p = blockIdx.x * NWARPS + warpId; p < NPTS; p += TOTWARPS) {
        // features: 4 coalesced float4 loads; lane L owns elems {4L+128c}
        const float4* f4 = reinterpret_cast<const float4*>(feats + (size_t)p * DIM);
        float4 f0 = f4[lane];
        float4 f1 = f4[lane + 32];
        float4 f2v = f4[lane + 64];
        float4 f3 = f4[lane + 96];

        // indices: broadcast loads; every lane holds all 9 row indices
        int lbl = l64 ? (int)reinterpret_cast<const long long*>(labels_v)[p]
                      : reinterpret_cast<const int*>(labels_v)[p];
        int nv0, nv1, nv2, nv3, nv4, nv5, nv6, nv7;
        if (n64) {
            const uint4* np = reinterpret_cast<const uint4*>(
                (const char*)negs_v + (size_t)p * 64);
            uint4 a = np[0], b = np[1], c = np[2], d = np[3];
            nv0 = (int)a.x; nv1 = (int)a.z;
            nv2 = (int)b.x; nv3 = (int)b.z;
            nv4 = (int)c.x; nv5 = (int)c.z;
            nv6 = (int)d.x; nv7 = (int)d.z;
        } else {
            const uint4* np = reinterpret_cast<const uint4*>(
                (const char*)negs_v + (size_t)p * 32);
            uint4 a = np[0], b = np[1];
            nv0 = (int)a.x; nv1 = (int)a.y; nv2 = (int)a.z; nv3 = (int)a.w;
            nv4 = (int)b.x; nv5 = (int)b.y; nv6 = (int)b.z; nv7 = (int)b.w;
        }
        // clamp (data guarantees <200; protects smem/gmem indexing)
        nv0 = min(nv0, NLBL - 1); nv1 = min(nv1, NLBL - 1);
        nv2 = min(nv2, NLBL - 1); nv3 = min(nv3, NLBL - 1);
        nv4 = min(nv4, NLBL - 1); nv5 = min(nv5, NLBL - 1);
        nv6 = min(nv6, NLBL - 1); nv7 = min(nv7, NLBL - 1);
        const int lblc = min(lbl, NLBL - 1);

        // positive anchor fp16 chunks from gmem table (L1/L2-served)
        const uint4* pp = &g_posU4[lblc * 64];
        uint4 pa = pp[lane];
        uint4 pb = pp[lane + 32];

        // ||f||^2 per-lane partial (fp32 exact)
        float f2p = f0.x * f0.x;
        f2p = fmaf(f0.y, f0.y, f2p); f2p = fmaf(f0.z, f0.z, f2p); f2p = fmaf(f0.w, f0.w, f2p);
        f2p = fmaf(f1.x, f1.x, f2p); f2p = fmaf(f1.y, f1.y, f2p); f2p = fmaf(f1.z, f1.z, f2p); f2p = fmaf(f1.w, f1.w, f2p);
        f2p = fmaf(f2v.x, f2v.x, f2p); f2p = fmaf(f2v.y, f2v.y, f2p); f2p = fmaf(f2v.z, f2v.z, f2p); f2p = fmaf(f2v.w, f2v.w, f2p);
        f2p = fmaf(f3.x, f3.x, f2p); f2p = fmaf(f3.y, f3.y, f2p); f2p = fmaf(f3.z, f3.z, f2p); f2p = fmaf(f3.w, f3.w, f2p);

        // features as f16x2 (same convention as staging)
        unsigned fh[8];
        fh[0] = cvt_f16x2(f0.y, f0.x);   fh[1] = cvt_f16x2(f0.w, f0.z);
        fh[2] = cvt_f16x2(f1.y, f1.x);   fh[3] = cvt_f16x2(f1.w, f1.z);
        fh[4] = cvt_f16x2(f2v.y, f2v.x); fh[5] = cvt_f16x2(f2v.w, f2v.z);
        fh[6] = cvt_f16x2(f3.y, f3.x);   fh[7] = cvt_f16x2(f3.w, f3.z);

        // positive dot (fp16 anchors): 8 HFMA2
        unsigned pacc = 0u;
        hfma2(pacc, pa.x, fh[0]); hfma2(pacc, pa.y, fh[1]);
        hfma2(pacc, pa.z, fh[2]); hfma2(pacc, pa.w, fh[3]);
        hfma2(pacc, pb.x, fh[4]); hfma2(pacc, pb.y, fh[5]);
        hfma2(pacc, pb.z, fh[6]); hfma2(pacc, pb.w, fh[7]);
        __half2 ph = *reinterpret_cast<__half2*>(&pacc);
        float2 pf = __half22float2(ph);
        float pos_t = fmaf(-2.f, pf.x + pf.y, f2p);   // lane partial of f2-2dot

        // 8 negative dots from e5m2 smem: 1 LDS.128 + 8 PRMT + 8 HFMA2 each
        int aidx[8] = {nv0, nv1, nv2, nv3, nv4, nv5, nv6, nv7};
        unsigned acc[8];
#pragma unroll
        for (int k = 0; k < 8; k++) {
            uint4 q = reinterpret_cast<const uint4*>(sNegB + aidx[k] * 512)[lane];
            unsigned a = 0u;
            hfma2(a, prmt0(q.x, 0x1404u), fh[0]); hfma2(a, prmt0(q.x, 0x3424u), fh[1]);
            hfma2(a, prmt0(q.y, 0x1404u), fh[2]); hfma2(a, prmt0(q.y, 0x3424u), fh[3]);
            hfma2(a, prmt0(q.z, 0x1404u), fh[4]); hfma2(a, prmt0(q.z, 0x3424u), fh[5]);
            hfma2(a, prmt0(q.w, 0x1404u), fh[6]); hfma2(a, prmt0(q.w, 0x3424u), fh[7]);
            acc[k] = a;
        }

        // pack 8 dots into 4 f16x2 and fold lane-partial f2 (t = f2 - 2d)
        unsigned f2h = cvt_f16x2(f2p, f2p);
        unsigned pk0 = hfma3(pairsum(acc[0], acc[1]), 0xC000C000u, f2h);
        unsigned pk1 = hfma3(pairsum(acc[2], acc[3]), 0xC000C000u, f2h);
        unsigned pk2 = hfma3(pairsum(acc[4], acc[5]), 0xC000C000u, f2h);
        unsigned pk3 = hfma3(pairsum(acc[6], acc[7]), 0xC000C000u, f2h);

        // butterfly: 4 packed f16x2 + 1 fp32 (pos)
#pragma unroll
        for (int off = 16; off > 0; off >>= 1) {
            pk0 = hadd2(pk0, __shfl_xor_sync(0xffffffffu, pk0, off));
            pk1 = hadd2(pk1, __shfl_xor_sync(0xffffffffu, pk1, off));
            pk2 = hadd2(pk2, __shfl_xor_sync(0xffffffffu, pk2, off));
            pk3 = hadd2(pk3, __shfl_xor_sync(0xffffffffu, pk3, off));
            pos_t += __shfl_xor_sync(0xffffffffu, pos_t, off);
        }

        // lane-parallel neg epilogue: lane k (0..7) handles negative k
        const int k = lane;
        unsigned pv = (k < 2) ? pk0 : (k < 4) ? pk1 : (k < 6) ? pk2 : pk3;
        __half2 hv = *reinterpret_cast<__half2*>(&pv);
        float tneg = (k & 1) ? __half2float(hv.y) : __half2float(hv.x);
        int nidx = (k == 0) ? nv0 : (k == 1) ? nv1 : (k == 2) ? nv2 :
                   (k == 3) ? nv3 : (k == 4) ? nv4 : (k == 5) ? nv5 :
                   (k == 6) ? nv6 : nv7;
        float d2n = tneg + sA2n[nidx];
        float distn = sqrt_approx(fmaxf(d2n, 0.f) + EPSF);
        float nd = (k < 8) ? distn : 0.f;
        nd += __shfl_xor_sync(0xffffffffu, nd, 1);
        nd += __shfl_xor_sync(0xffffffffu, nd, 2);
        nd += __shfl_xor_sync(0xffffffffu, nd, 4);

        if (lane == 0) {
            float d2pv = pos_t + sA2p[lblc];
            float distp = sqrt_approx(fmaxf(d2pv, 0.f) + EPSF);
            bool  valid = (lbl != IGNORE_LBL);
            float pl = valid ? fmaxf(distp, 0.f) : 0.f;           // POS_THRESH=0
            float nl = valid ? fmaxf(NEG_TH - nd * 0.125f, 0.f) : 0.f;
            if (writeArrays) {
                out[1 + p]        = pl;
                out[1 + NPTS + p] = nl;
            }
            sumPos += pl;
            sumNeg += nl;
        }
    }

    // ---- block partials
    if (lane == 0) {
        sRed[warpId]          = sumPos;
        sRed[NWARPS + warpId] = sumNeg;
    }
    __syncthreads();
    if (threadIdx.x < 32) {
        float sp = wred(sRed[threadIdx.x]);
        float sn = wred(sRed[NWARPS + threadIdx.x]);
        if (threadIdx.x == 0) {
            g_ppos[blockIdx.x] = sp;
            g_pneg[blockIdx.x] = sn;
        }
    }

    // ---- last-block grid reduction
    if (threadIdx.x == 0) {
        __threadfence();
        unsigned int c = atomicAdd(&g_count, 1u);
        sIsLast = (c == (unsigned)(BLOCKS - 1)) ? 1 : 0;
    }
    __syncthreads();
    if (sIsLast) {
        __threadfence();
        float sp = 0.f, sn = 0.f;
        if (threadIdx.x < BLOCKS) {
            sp = g_ppos[threadIdx.x];
            sn = g_pneg[threadIdx.x];
        }
        if (warpId < 5) {
            sp = wred(sp);
            sn = wred(sn);
            if (lane == 0) { sRed[warpId] = sp; sRed[8 + warpId] = sn; }
        }
        __syncthreads();
        if (threadIdx.x == 0) {
            float tp = 0.f, tn = 0.f;
#pragma unroll
            for (int i = 0; i < 5; i++) { tp += sRed[i]; tn += sRed[8 + i]; }
            out[0] = (tp + tn) * (1.0f / (float)NPTS);
            atomicExch(&g_count, 0u);      // reset for next graph replay
        }
    }
}

extern "C" void kernel_launch(void* const* d_in, const int* in_sizes, int n_in,
                              void* d_out, int out_size) {
    const float* feats   = (const float*)d_in[0];
    const void*  labels  = d_in[1];
    const float* anchors = (const float*)d_in[2];
    const void*  negs    = d_in[3];
    float* out = (float*)d_out;

    const int writeArrays = (out_size >= 1 + 2 * NPTS) ? 1 : 0;

    cudaFuncSetAttribute(loss_kernel, cudaFuncAttributeMaxDynamicSharedMemorySize, SMEM_BYTES);
    loss_kernel<<<BLOCKS, NTHREADS, SMEM_BYTES>>>(feats, labels, anchors, negs, out, writeArrays);
}

// round 6
// speedup vs baseline: 1.6992x; 1.0813x over previous
#include <cuda_runtime.h>
#include <cuda_fp16.h>
#include <stdint.h>

#define NPTS 262144
#define DIM 512
#define NLBL 200
#define KNEG 8
#define EPSF 1e-7f
#define NEG_TH 0.85f
#define IGNORE_LBL 255
#define D2SUB_GUARD 64.0f   // true d2_sub >= computed - 60 ; >=64 => dist >= 2 > 0.85

constexpr int BLOCKS   = 152;
constexpr int NTHREADS = 1024;
constexpr int NWARPS   = NTHREADS / 32;
constexpr int TOTWARPS = BLOCKS * NWARPS;

// dynamic smem: compact e5m2 subset table (128B/row) + a2 tables + scratch
constexpr int SM_SUB_BYTES = NLBL * 128;            // 25600 B
constexpr int SM_A2P_OFF   = SM_SUB_BYTES;          // fp16-consistent a2 (pos)
constexpr int SM_A2N_OFF   = SM_A2P_OFF + 1024;     // subset-consistent a2 (neg)
constexpr int SM_RED_OFF   = SM_A2N_OFF + 1024;
constexpr int SMEM_BYTES   = SM_RED_OFF + 2 * NWARPS * 4;

// fp16 positive-anchor table in gmem (L1-resident: smem is small now)
__device__ uint4 g_posU4[NLBL * 64];

__device__ float g_ppos[BLOCKS];
__device__ float g_pneg[BLOCKS];
__device__ unsigned int g_count = 0;

// ---------------------------------------------------------------------------
// helpers
// ---------------------------------------------------------------------------
__device__ __forceinline__ unsigned cvt_f16x2(float hi, float lo) {
    unsigned r;
    asm("cvt.rn.f16x2.f32 %0, %1, %2;" : "=r"(r) : "f"(hi), "f"(lo));
    return r;
}
__device__ __forceinline__ void hfma2(unsigned& acc, unsigned a, unsigned b) {
    asm("fma.rn.f16x2 %0, %1, %2, %0;" : "+r"(acc) : "r"(a), "r"(b));
}
__device__ __forceinline__ unsigned hfma3(unsigned a, unsigned b, unsigned c) {
    unsigned r;
    asm("fma.rn.f16x2 %0, %1, %2, %3;" : "=r"(r) : "r"(a), "r"(b), "r"(c));
    return r;
}
__device__ __forceinline__ unsigned hadd2(unsigned a, unsigned b) {
    unsigned r;
    asm("add.rn.f16x2 %0, %1, %2;" : "=r"(r) : "r"(a), "r"(b));
    return r;
}
__device__ __forceinline__ unsigned prmt(unsigned a, unsigned b, unsigned sel) {
    unsigned r;
    asm("prmt.b32 %0, %1, %2, %3;" : "=r"(r) : "r"(a), "r"(b), "r"(sel));
    return r;
}
__device__ __forceinline__ unsigned prmt0(unsigned a, unsigned sel) {
    unsigned r;
    asm("prmt.b32 %0, %1, %2, %3;" : "=r"(r) : "r"(a), "r"(0u), "r"(sel));
    return r;
}
__device__ __forceinline__ unsigned pairsum(unsigned a, unsigned b) {
    return hadd2(prmt(a, b, 0x5410u), prmt(a, b, 0x7632u));
}
__device__ __forceinline__ float sqrt_approx(float x) {
    float r;
    asm("sqrt.approx.f32 %0, %1;" : "=f"(r) : "f"(x));
    return r;
}
__device__ __forceinline__ float wred(float v) {
#pragma unroll
    for (int off = 16; off > 0; off >>= 1)
        v += __shfl_xor_sync(0xffffffffu, v, off);
    return v;
}

// ---------------------------------------------------------------------------
// Single fused kernel.
// ---------------------------------------------------------------------------
__global__ __launch_bounds__(NTHREADS, 1)
void loss_kernel(const float* __restrict__ feats,
                 const void*  __restrict__ labels_v,
                 const float* __restrict__ anchors,
                 const void*  __restrict__ negs_v,
                 float* __restrict__ out,
                 int writeArrays) {
    extern __shared__ unsigned char smem[];
    unsigned* sSub = reinterpret_cast<unsigned*>(smem);        // [NLBL*32]
    float* sA2p = reinterpret_cast<float*>(smem + SM_A2P_OFF);
    float* sA2n = reinterpret_cast<float*>(smem + SM_A2N_OFF);
    float* sRed = reinterpret_cast<float*>(smem + SM_RED_OFF);
    __shared__ int sFlags;
    __shared__ int sIsLast;

    const int warpId = threadIdx.x >> 5;
    const int lane   = threadIdx.x & 31;

    // ---- dtype sniff: values nonneg < 200 -> odd int32 words zero iff int64
    if (warpId == 0) {
        const int* li = reinterpret_cast<const int*>(labels_v);
        const int* ni = reinterpret_cast<const int*>(negs_v);
        int lnz = li[2 * lane + 1] | li[2 * lane + 65];
        int nnz = ni[2 * lane + 1] | ni[2 * lane + 65];
        unsigned lb = __ballot_sync(0xffffffffu, lnz != 0);
        unsigned nb = __ballot_sync(0xffffffffu, nnz != 0);
        if (lane == 0) sFlags = ((lb == 0u) ? 1 : 0) | ((nb == 0u) ? 2 : 0);
    }

    // ---- stage anchors: fp16 pos table (gmem) + e5m2 subset table (smem) + a2s
    for (int r = warpId; r < NLBL; r += NWARPS) {
        const float4* src = reinterpret_cast<const float4*>(anchors + r * DIM);
        unsigned w[8];
        float a2p = 0.f;
#pragma unroll
        for (int c = 0; c < 4; c++) {
            float4 v = src[lane + 32 * c];
            w[2 * c]     = cvt_f16x2(v.y, v.x);   // {lo: elem 4L+128c, hi: +1}
            w[2 * c + 1] = cvt_f16x2(v.w, v.z);
        }
#pragma unroll
        for (int j = 0; j < 8; j++) {
            __half2 h = *reinterpret_cast<__half2*>(&w[j]);
            float2 q = __half22float2(h);
            a2p = fmaf(q.x, q.x, a2p);
            a2p = fmaf(q.y, q.y, a2p);
        }
        // e5m2 subset word: rounded high bytes of lo-halves of w[0],w[2],w[4],w[6]
        unsigned w0r = w[0] + 0x0080u;
        unsigned w2r = w[2] + 0x0080u;
        unsigned w4r = w[4] + 0x0080u;
        unsigned w6r = w[6] + 0x0080u;
        unsigned x01 = prmt(w0r, w2r, 0x0051u);
        unsigned x23 = prmt(w4r, w6r, 0x0051u);
        unsigned subw = prmt(x01, x23, 0x5410u);
        // subset-consistent a2 (decode exactly like main loop)
        unsigned plo = prmt0(subw, 0x1404u);
        unsigned phi = prmt0(subw, 0x3424u);
        __half2 hlo = *reinterpret_cast<__half2*>(&plo);
        __half2 hhi = *reinterpret_cast<__half2*>(&phi);
        float2 qlo = __half22float2(hlo);
        float2 qhi = __half22float2(hhi);
        float a2n = qlo.x * qlo.x;
        a2n = fmaf(qlo.y, qlo.y, a2n);
        a2n = fmaf(qhi.x, qhi.x, a2n);
        a2n = fmaf(qhi.y, qhi.y, a2n);

        sSub[r * 32 + lane] = subw;
        g_posU4[r * 64 + lane]      = make_uint4(w[0], w[1], w[2], w[3]);
        g_posU4[r * 64 + 32 + lane] = make_uint4(w[4], w[5], w[6], w[7]);
        float s2p = wred(a2p);
        float s2n = wred(a2n);
        if (lane == 0) { sA2p[r] = s2p; sA2n[r] = s2n; }
    }
    __syncthreads();

    const bool l64 = (sFlags & 1) != 0;
    const bool n64 = (sFlags & 2) != 0;

    float sumPos = 0.f, sumNeg = 0.f;

    for (int p = blockIdx.x * NWARPS + warpId; p < NPTS; p += TOTWARPS) {
        // features: 4 coalesced float4 loads; lane L owns elems {4L+128c..+3}
        const float4* f4 = reinterpret_cast<const float4*>(feats + (size_t)p * DIM);
        float4 f0 = f4[lane];
        float4 f1 = f4[lane + 32];
        float4 f2v = f4[lane + 64];
        float4 f3 = f4[lane + 96];

        // indices: broadcast loads; every lane holds all 9 row indices
        int lbl = l64 ? (int)reinterpret_cast<const long long*>(labels_v)[p]
                      : reinterpret_cast<const int*>(labels_v)[p];
        int nv0, nv1, nv2, nv3, nv4, nv5, nv6, nv7;
        if (n64) {
            const uint4* np = reinterpret_cast<const uint4*>(
                (const char*)negs_v + (size_t)p * 64);
            uint4 a = np[0], b = np[1], c = np[2], d = np[3];
            nv0 = (int)a.x; nv1 = (int)a.z;
            nv2 = (int)b.x; nv3 = (int)b.z;
            nv4 = (int)c.x; nv5 = (int)c.z;
            nv6 = (int)d.x; nv7 = (int)d.z;
        } else {
            const uint4* np = reinterpret_cast<const uint4*>(
                (const char*)negs_v + (size_t)p * 32);
            uint4 a = np[0], b = np[1];
            nv0 = (int)a.x; nv1 = (int)a.y; nv2 = (int)a.z; nv3 = (int)a.w;
            nv4 = (int)b.x; nv5 = (int)b.y; nv6 = (int)b.z; nv7 = (int)b.w;
        }
        nv0 = min(nv0, NLBL - 1); nv1 = min(nv1, NLBL - 1);
        nv2 = min(nv2, NLBL - 1); nv3 = min(nv3, NLBL - 1);
        nv4 = min(nv4, NLBL - 1); nv5 = min(nv5, NLBL - 1);
        nv6 = min(nv6, NLBL - 1); nv7 = min(nv7, NLBL - 1);
        const int lblc = min(lbl, NLBL - 1);

        // positive anchor fp16 from L1-resident gmem table
        const uint4* pp = &g_posU4[lblc * 64];
        uint4 pa = pp[lane];
        uint4 pb = pp[lane + 32];

        // ||f||^2 per-lane partial (fp32 exact) + subset partial
        float f2p = f0.x * f0.x;
        f2p = fmaf(f0.y, f0.y, f2p); f2p = fmaf(f0.z, f0.z, f2p); f2p = fmaf(f0.w, f0.w, f2p);
        f2p = fmaf(f1.x, f1.x, f2p); f2p = fmaf(f1.y, f1.y, f2p); f2p = fmaf(f1.z, f1.z, f2p); f2p = fmaf(f1.w, f1.w, f2p);
        f2p = fmaf(f2v.x, f2v.x, f2p); f2p = fmaf(f2v.y, f2v.y, f2p); f2p = fmaf(f2v.z, f2v.z, f2p); f2p = fmaf(f2v.w, f2v.w, f2p);
        f2p = fmaf(f3.x, f3.x, f2p); f2p = fmaf(f3.y, f3.y, f2p); f2p = fmaf(f3.z, f3.z, f2p); f2p = fmaf(f3.w, f3.w, f2p);
        float f2s = f0.x * f0.x;
        f2s = fmaf(f1.x, f1.x, f2s);
        f2s = fmaf(f2v.x, f2v.x, f2s);
        f2s = fmaf(f3.x, f3.x, f2s);

        // features as f16x2
        unsigned fh[8];
        fh[0] = cvt_f16x2(f0.y, f0.x);   fh[1] = cvt_f16x2(f0.w, f0.z);
        fh[2] = cvt_f16x2(f1.y, f1.x);   fh[3] = cvt_f16x2(f1.w, f1.z);
        fh[4] = cvt_f16x2(f2v.y, f2v.x); fh[5] = cvt_f16x2(f2v.w, f2v.z);
        fh[6] = cvt_f16x2(f3.y, f3.x);   fh[7] = cvt_f16x2(f3.w, f3.z);
        // subset feature pairs: {f(4L), f(4L+128)}, {f(4L+256), f(4L+384)}
        unsigned fs0 = prmt(fh[0], fh[2], 0x5410u);
        unsigned fs1 = prmt(fh[4], fh[6], 0x5410u);

        // positive dot: 8 HFMA2
        unsigned pacc = 0u;
        hfma2(pacc, pa.x, fh[0]); hfma2(pacc, pa.y, fh[1]);
        hfma2(pacc, pa.z, fh[2]); hfma2(pacc, pa.w, fh[3]);
        hfma2(pacc, pb.x, fh[4]); hfma2(pacc, pb.y, fh[5]);
        hfma2(pacc, pb.z, fh[6]); hfma2(pacc, pb.w, fh[7]);
        __half2 ph = *reinterpret_cast<__half2*>(&pacc);
        float2 pf = __half22float2(ph);
        float pos_t = fmaf(-2.f, pf.x + pf.y, f2p);

        // 8 negative subset dots: 1 LDS.32 + 2 PRMT + 2 HFMA2 each
        int aidx[8] = {nv0, nv1, nv2, nv3, nv4, nv5, nv6, nv7};
        unsigned acc[8];
#pragma unroll
        for (int k = 0; k < 8; k++) {
            unsigned q = sSub[aidx[k] * 32 + lane];
            unsigned a = 0u;
            hfma2(a, prmt0(q, 0x1404u), fs0);
            hfma2(a, prmt0(q, 0x3424u), fs1);
            acc[k] = a;
        }

        // pack into 4 f16x2, fold lane-partial subset f2 (t = f2s - 2*dot)
        unsigned f2h = cvt_f16x2(f2s, f2s);
        unsigned pk0 = hfma3(pairsum(acc[0], acc[1]), 0xC000C000u, f2h);
        unsigned pk1 = hfma3(pairsum(acc[2], acc[3]), 0xC000C000u, f2h);
        unsigned pk2 = hfma3(pairsum(acc[4], acc[5]), 0xC000C000u, f2h);
        unsigned pk3 = hfma3(pairsum(acc[6], acc[7]), 0xC000C000u, f2h);

        // butterfly: 4 packed f16x2 + 1 fp32 (pos)
#pragma unroll
        for (int off = 16; off > 0; off >>= 1) {
            pk0 = hadd2(pk0, __shfl_xor_sync(0xffffffffu, pk0, off));
            pk1 = hadd2(pk1, __shfl_xor_sync(0xffffffffu, pk1, off));
            pk2 = hadd2(pk2, __shfl_xor_sync(0xffffffffu, pk2, off));
            pk3 = hadd2(pk3, __shfl_xor_sync(0xffffffffu, pk3, off));
            pos_t += __shfl_xor_sync(0xffffffffu, pos_t, off);
        }

        // lane-parallel guard: lane k<8 checks neg k's subset d2 lower bound
        const int k = lane;
        unsigned pv = (k < 2) ? pk0 : (k < 4) ? pk1 : (k < 6) ? pk2 : pk3;
        __half2 hv = *reinterpret_cast<__half2*>(&pv);
        float tneg = (k & 1) ? __half2float(hv.y) : __half2float(hv.x);
        int nidx = (k == 0) ? nv0 : (k == 1) ? nv1 : (k == 2) ? nv2 :
                   (k == 3) ? nv3 : (k == 4) ? nv4 : (k == 5) ? nv5 :
                   (k == 6) ? nv6 : nv7;
        float d2sub = tneg + sA2n[nidx];
        bool okk = (k < 8) ? (d2sub >= D2SUB_GUARD) : true;
        bool fast = (__ballot_sync(0xffffffffu, okk) == 0xffffffffu);

        float nl = 0.f;
        if (!fast) {
            // exact fp32 fallback (statistically never taken; keeps the
            // bound-based zero unconditional rather than data-lucky)
            float nsum = 0.f;
            for (int kk = 0; kk < 8; kk++) {
                int idx = aidx[kk];
                const float4* ap = reinterpret_cast<const float4*>(anchors + idx * DIM);
                float4 a0 = ap[lane], a1 = ap[lane + 32],
                       a2 = ap[lane + 64], a3 = ap[lane + 96];
                float t = f2p;
                t = fmaf(a0.x, fmaf(-2.f, f0.x, a0.x), t);
                t = fmaf(a0.y, fmaf(-2.f, f0.y, a0.y), t);
                t = fmaf(a0.z, fmaf(-2.f, f0.z, a0.z), t);
                t = fmaf(a0.w, fmaf(-2.f, f0.w, a0.w), t);
                t = fmaf(a1.x, fmaf(-2.f, f1.x, a1.x), t);
                t = fmaf(a1.y, fmaf(-2.f, f1.y, a1.y), t);
                t = fmaf(a1.z, fmaf(-2.f, f1.z, a1.z), t);
                t = fmaf(a1.w, fmaf(-2.f, f1.w, a1.w), t);
                t = fmaf(a2.x, fmaf(-2.f, f2v.x, a2.x), t);
                t = fmaf(a2.y, fmaf(-2.f, f2v.y, a2.y), t);
                t = fmaf(a2.z, fmaf(-2.f, f2v.z, a2.z), t);
                t = fmaf(a2.w, fmaf(-2.f, f2v.w, a2.w), t);
                t = fmaf(a3.x, fmaf(-2.f, f3.x, a3.x), t);
                t = fmaf(a3.y, fmaf(-2.f, f3.y, a3.y), t);
                t = fmaf(a3.z, fmaf(-2.f, f3.z, a3.z), t);
                t = fmaf(a3.w, fmaf(-2.f, f3.w, a3.w), t);
                float d2 = wred(t);
                nsum += sqrtf(fmaxf(d2, 0.f) + EPSF);
            }
            nl = fmaxf(NEG_TH - nsum * 0.125f, 0.f);
        }

        if (lane == 0) {
            float d2pv = pos_t + sA2p[lblc];
            float distp = sqrt_approx(fmaxf(d2pv, 0.f) + EPSF);
            bool  valid = (lbl != IGNORE_LBL);
            float pl = valid ? fmaxf(distp, 0.f) : 0.f;        // POS_THRESH=0
            float nlv = valid ? nl : 0.f;
            if (writeArrays) {
                out[1 + p]        = pl;
                out[1 + NPTS + p] = nlv;
            }
            sumPos += pl;
            sumNeg += nlv;
        }
    }

    // ---- block partials
    if (lane == 0) {
        sRed[warpId]          = sumPos;
        sRed[NWARPS + warpId] = sumNeg;
    }
    __syncthreads();
    if (threadIdx.x < 32) {
        float sp = wred(sRed[threadIdx.x]);
        float sn = wred(sRed[NWARPS + threadIdx.x]);
        if (threadIdx.x == 0) {
            g_ppos[blockIdx.x] = sp;
            g_pneg[blockIdx.x] = sn;
        }
    }

    // ---- last-block grid reduction
    if (threadIdx.x == 0) {
        __threadfence();
        unsigned int c = atomicAdd(&g_count, 1u);
        sIsLast = (c == (unsigned)(BLOCKS - 1)) ? 1 : 0;
    }
    __syncthreads();
    if (sIsLast) {
        __threadfence();
        float sp = 0.f, sn = 0.f;
        if (threadIdx.x < BLOCKS) {
            sp = g_ppos[threadIdx.x];
            sn = g_pneg[threadIdx.x];
        }
        if (warpId < 5) {
            sp = wred(sp);
            sn = wred(sn);
            if (lane == 0) { sRed[warpId] = sp; sRed[8 + warpId] = sn; }
        }
        __syncthreads();
        if (threadIdx.x == 0) {
            float tp = 0.f, tn = 0.f;
#pragma unroll
            for (int i = 0; i < 5; i++) { tp += sRed[i]; tn += sRed[8 + i]; }
            out[0] = (tp + tn) * (1.0f / (float)NPTS);
            atomicExch(&g_count, 0u);      // reset for next graph replay
        }
    }
}

extern "C" void kernel_launch(void* const* d_in, const int* in_sizes, int n_in,
                              void* d_out, int out_size) {
    const float* feats   = (const float*)d_in[0];
    const void*  labels  = d_in[1];
    const float* anchors = (const float*)d_in[2];
    const void*  negs    = d_in[3];
    float* out = (float*)d_out;

    const int writeArrays = (out_size >= 1 + 2 * NPTS) ? 1 : 0;

    cudaFuncSetAttribute(loss_kernel, cudaFuncAttributeMaxDynamicSharedMemorySize, SMEM_BYTES);
    loss_kernel<<<BLOCKS, NTHREADS, SMEM_BYTES>>>(feats, labels, anchors, negs, out, writeArrays);
}

// round 7
// speedup vs baseline: 1.8415x; 1.0837x over previous
#include <cuda_runtime.h>
#include <cuda_fp16.h>
#include <stdint.h>

#define NPTS 262144
#define DIM 512
#define NLBL 200
#define KNEG 8
#define EPSF 1e-7f
#define NEG_TH 0.85f
#define IGNORE_LBL 255
#define D2SUB_GUARD 64.0f   // true d2_sub >= computed - 60 ; >=64 => dist >= 2 > 0.85

constexpr int BLOCKS   = 152;
constexpr int NTHREADS = 768;            // 85-reg budget; enables 1-deep prefetch
constexpr int NWARPS   = NTHREADS / 32;  // 24
constexpr int TOTWARPS = BLOCKS * NWARPS;

// dynamic smem: compact e5m2 subset table (128B/row) + a2 tables + scratch
constexpr int SM_SUB_BYTES = NLBL * 128;            // 25600 B
constexpr int SM_A2P_OFF   = SM_SUB_BYTES;
constexpr int SM_A2N_OFF   = SM_A2P_OFF + 1024;
constexpr int SM_RED_OFF   = SM_A2N_OFF + 1024;
constexpr int SMEM_BYTES   = SM_RED_OFF + 2 * NWARPS * 4;

// fp16 positive-anchor table in gmem (L1-cached; features use streaming loads)
__device__ uint4 g_posU4[NLBL * 64];

__device__ float g_ppos[BLOCKS];
__device__ float g_pneg[BLOCKS];
__device__ unsigned int g_count = 0;

// ---------------------------------------------------------------------------
// helpers
// ---------------------------------------------------------------------------
__device__ __forceinline__ unsigned cvt_f16x2(float hi, float lo) {
    unsigned r;
    asm("cvt.rn.f16x2.f32 %0, %1, %2;" : "=r"(r) : "f"(hi), "f"(lo));
    return r;
}
__device__ __forceinline__ void hfma2(unsigned& acc, unsigned a, unsigned b) {
    asm("fma.rn.f16x2 %0, %1, %2, %0;" : "+r"(acc) : "r"(a), "r"(b));
}
__device__ __forceinline__ unsigned hfma3(unsigned a, unsigned b, unsigned c) {
    unsigned r;
    asm("fma.rn.f16x2 %0, %1, %2, %3;" : "=r"(r) : "r"(a), "r"(b), "r"(c));
    return r;
}
__device__ __forceinline__ unsigned hadd2(unsigned a, unsigned b) {
    unsigned r;
    asm("add.rn.f16x2 %0, %1, %2;" : "=r"(r) : "r"(a), "r"(b));
    return r;
}
__device__ __forceinline__ unsigned prmt(unsigned a, unsigned b, unsigned sel) {
    unsigned r;
    asm("prmt.b32 %0, %1, %2, %3;" : "=r"(r) : "r"(a), "r"(b), "r"(sel));
    return r;
}
__device__ __forceinline__ unsigned prmt0(unsigned a, unsigned sel) {
    unsigned r;
    asm("prmt.b32 %0, %1, %2, %3;" : "=r"(r) : "r"(a), "r"(0u), "r"(sel));
    return r;
}
__device__ __forceinline__ unsigned pairsum(unsigned a, unsigned b) {
    return hadd2(prmt(a, b, 0x5410u), prmt(a, b, 0x7632u));
}
__device__ __forceinline__ float sqrt_approx(float x) {
    float r;
    asm("sqrt.approx.f32 %0, %1;" : "=f"(r) : "f"(x));
    return r;
}
__device__ __forceinline__ float wred(float v) {
#pragma unroll
    for (int off = 16; off > 0; off >>= 1)
        v += __shfl_xor_sync(0xffffffffu, v, off);
    return v;
}
__device__ __forceinline__ float4 ldcs4(const float4* p) {
    float4 v;
    asm("ld.global.cs.v4.f32 {%0,%1,%2,%3}, [%4];"
        : "=f"(v.x), "=f"(v.y), "=f"(v.z), "=f"(v.w) : "l"(p));
    return v;
}

// ---------------------------------------------------------------------------
// Single fused kernel.
// ---------------------------------------------------------------------------
__global__ __launch_bounds__(NTHREADS, 1)
void loss_kernel(const float* __restrict__ feats,
                 const void*  __restrict__ labels_v,
                 const float* __restrict__ anchors,
                 const void*  __restrict__ negs_v,
                 float* __restrict__ out,
                 int writeArrays) {
    extern __shared__ unsigned char smem[];
    unsigned* sSub = reinterpret_cast<unsigned*>(smem);
    float* sA2p = reinterpret_cast<float*>(smem + SM_A2P_OFF);
    float* sA2n = reinterpret_cast<float*>(smem + SM_A2N_OFF);
    float* sRed = reinterpret_cast<float*>(smem + SM_RED_OFF);
    __shared__ int sFlags;
    __shared__ int sIsLast;

    const int warpId = threadIdx.x >> 5;
    const int lane   = threadIdx.x & 31;

    // ---- dtype sniff: values nonneg < 200 -> odd int32 words zero iff int64
    if (warpId == 0) {
        const int* li = reinterpret_cast<const int*>(labels_v);
        const int* ni = reinterpret_cast<const int*>(negs_v);
        int lnz = li[2 * lane + 1] | li[2 * lane + 65];
        int nnz = ni[2 * lane + 1] | ni[2 * lane + 65];
        unsigned lb = __ballot_sync(0xffffffffu, lnz != 0);
        unsigned nb = __ballot_sync(0xffffffffu, nnz != 0);
        if (lane == 0) sFlags = ((lb == 0u) ? 1 : 0) | ((nb == 0u) ? 2 : 0);
    }

    // ---- stage anchors: fp16 pos table (gmem) + e5m2 subset table (smem) + a2s
    for (int r = warpId; r < NLBL; r += NWARPS) {
        const float4* src = reinterpret_cast<const float4*>(anchors + r * DIM);
        unsigned w[8];
        float a2p = 0.f;
#pragma unroll
        for (int c = 0; c < 4; c++) {
            float4 v = src[lane + 32 * c];
            w[2 * c]     = cvt_f16x2(v.y, v.x);
            w[2 * c + 1] = cvt_f16x2(v.w, v.z);
        }
#pragma unroll
        for (int j = 0; j < 8; j++) {
            __half2 h = *reinterpret_cast<__half2*>(&w[j]);
            float2 q = __half22float2(h);
            a2p = fmaf(q.x, q.x, a2p);
            a2p = fmaf(q.y, q.y, a2p);
        }
        unsigned w0r = w[0] + 0x0080u;
        unsigned w2r = w[2] + 0x0080u;
        unsigned w4r = w[4] + 0x0080u;
        unsigned w6r = w[6] + 0x0080u;
        unsigned x01 = prmt(w0r, w2r, 0x0051u);
        unsigned x23 = prmt(w4r, w6r, 0x0051u);
        unsigned subw = prmt(x01, x23, 0x5410u);
        unsigned plo = prmt0(subw, 0x1404u);
        unsigned phi = prmt0(subw, 0x3424u);
        __half2 hlo = *reinterpret_cast<__half2*>(&plo);
        __half2 hhi = *reinterpret_cast<__half2*>(&phi);
        float2 qlo = __half22float2(hlo);
        float2 qhi = __half22float2(hhi);
        float a2n = qlo.x * qlo.x;
        a2n = fmaf(qlo.y, qlo.y, a2n);
        a2n = fmaf(qhi.x, qhi.x, a2n);
        a2n = fmaf(qhi.y, qhi.y, a2n);

        sSub[r * 32 + lane] = subw;
        g_posU4[r * 64 + lane]      = make_uint4(w[0], w[1], w[2], w[3]);
        g_posU4[r * 64 + 32 + lane] = make_uint4(w[4], w[5], w[6], w[7]);
        float s2p = wred(a2p);
        float s2n = wred(a2n);
        if (lane == 0) { sA2p[r] = s2p; sA2n[r] = s2n; }
    }
    __syncthreads();

    const bool l64 = (sFlags & 1) != 0;
    const bool n64 = (sFlags & 2) != 0;

    float sumPos = 0.f, sumNeg = 0.f;

    int p = blockIdx.x * NWARPS + warpId;
    float4 f0, f1, f2v, f3;
    if (p < NPTS) {
        const float4* f4 = reinterpret_cast<const float4*>(feats + (size_t)p * DIM);
        f0  = ldcs4(f4 + lane);
        f1  = ldcs4(f4 + lane + 32);
        f2v = ldcs4(f4 + lane + 64);
        f3  = ldcs4(f4 + lane + 96);
    }

    for (; p < NPTS; ) {
        const int pn = p + TOTWARPS;

        // indices for current point (broadcast loads)
        int lbl = l64 ? (int)reinterpret_cast<const long long*>(labels_v)[p]
                      : reinterpret_cast<const int*>(labels_v)[p];
        int nv0, nv1, nv2, nv3, nv4, nv5, nv6, nv7;
        if (n64) {
            const uint4* np = reinterpret_cast<const uint4*>(
                (const char*)negs_v + (size_t)p * 64);
            uint4 a = np[0], b = np[1], c = np[2], d = np[3];
            nv0 = (int)a.x; nv1 = (int)a.z;
            nv2 = (int)b.x; nv3 = (int)b.z;
            nv4 = (int)c.x; nv5 = (int)c.z;
            nv6 = (int)d.x; nv7 = (int)d.z;
        } else {
            const uint4* np = reinterpret_cast<const uint4*>(
                (const char*)negs_v + (size_t)p * 32);
            uint4 a = np[0], b = np[1];
            nv0 = (int)a.x; nv1 = (int)a.y; nv2 = (int)a.z; nv3 = (int)a.w;
            nv4 = (int)b.x; nv5 = (int)b.y; nv6 = (int)b.z; nv7 = (int)b.w;
        }
        nv0 = min(nv0, NLBL - 1); nv1 = min(nv1, NLBL - 1);
        nv2 = min(nv2, NLBL - 1); nv3 = min(nv3, NLBL - 1);
        nv4 = min(nv4, NLBL - 1); nv5 = min(nv5, NLBL - 1);
        nv6 = min(nv6, NLBL - 1); nv7 = min(nv7, NLBL - 1);
        const int lblc = min(lbl, NLBL - 1);

        // positive anchor fp16 (cached; L1-resident thanks to ldcs features)
        const uint4* pp = &g_posU4[lblc * 64];
        uint4 pa = pp[lane];
        uint4 pb = pp[lane + 32];

        // ||f||^2 + subset partial + fh conversion (consumes fp32 features)
        float f2p = f0.x * f0.x;
        f2p = fmaf(f0.y, f0.y, f2p); f2p = fmaf(f0.z, f0.z, f2p); f2p = fmaf(f0.w, f0.w, f2p);
        f2p = fmaf(f1.x, f1.x, f2p); f2p = fmaf(f1.y, f1.y, f2p); f2p = fmaf(f1.z, f1.z, f2p); f2p = fmaf(f1.w, f1.w, f2p);
        f2p = fmaf(f2v.x, f2v.x, f2p); f2p = fmaf(f2v.y, f2v.y, f2p); f2p = fmaf(f2v.z, f2v.z, f2p); f2p = fmaf(f2v.w, f2v.w, f2p);
        f2p = fmaf(f3.x, f3.x, f2p); f2p = fmaf(f3.y, f3.y, f2p); f2p = fmaf(f3.z, f3.z, f2p); f2p = fmaf(f3.w, f3.w, f2p);
        float f2s = f0.x * f0.x;
        f2s = fmaf(f1.x, f1.x, f2s);
        f2s = fmaf(f2v.x, f2v.x, f2s);
        f2s = fmaf(f3.x, f3.x, f2s);

        unsigned fh[8];
        fh[0] = cvt_f16x2(f0.y, f0.x);   fh[1] = cvt_f16x2(f0.w, f0.z);
        fh[2] = cvt_f16x2(f1.y, f1.x);   fh[3] = cvt_f16x2(f1.w, f1.z);
        fh[4] = cvt_f16x2(f2v.y, f2v.x); fh[5] = cvt_f16x2(f2v.w, f2v.z);
        fh[6] = cvt_f16x2(f3.y, f3.x);   fh[7] = cvt_f16x2(f3.w, f3.z);
        unsigned fs0 = prmt(fh[0], fh[2], 0x5410u);
        unsigned fs1 = prmt(fh[4], fh[6], 0x5410u);

        // ---- PREFETCH next point's features (fp32 regs are now dead)
        if (pn < NPTS) {
            const float4* f4n = reinterpret_cast<const float4*>(feats + (size_t)pn * DIM);
            f0  = ldcs4(f4n + lane);
            f1  = ldcs4(f4n + lane + 32);
            f2v = ldcs4(f4n + lane + 64);
            f3  = ldcs4(f4n + lane + 96);
        }

        // positive dot: 8 HFMA2
        unsigned pacc = 0u;
        hfma2(pacc, pa.x, fh[0]); hfma2(pacc, pa.y, fh[1]);
        hfma2(pacc, pa.z, fh[2]); hfma2(pacc, pa.w, fh[3]);
        hfma2(pacc, pb.x, fh[4]); hfma2(pacc, pb.y, fh[5]);
        hfma2(pacc, pb.z, fh[6]); hfma2(pacc, pb.w, fh[7]);
        __half2 ph = *reinterpret_cast<__half2*>(&pacc);
        float2 pf = __half22float2(ph);
        float pos_t = fmaf(-2.f, pf.x + pf.y, f2p);

        // 8 negative subset dots: 1 LDS.32 + 2 PRMT + 2 HFMA2 each
        int aidx[8] = {nv0, nv1, nv2, nv3, nv4, nv5, nv6, nv7};
        unsigned acc[8];
#pragma unroll
        for (int k = 0; k < 8; k++) {
            unsigned q = sSub[aidx[k] * 32 + lane];
            unsigned a = 0u;
            hfma2(a, prmt0(q, 0x1404u), fs0);
            hfma2(a, prmt0(q, 0x3424u), fs1);
            acc[k] = a;
        }

        unsigned f2h = cvt_f16x2(f2s, f2s);
        unsigned pk0 = hfma3(pairsum(acc[0], acc[1]), 0xC000C000u, f2h);
        unsigned pk1 = hfma3(pairsum(acc[2], acc[3]), 0xC000C000u, f2h);
        unsigned pk2 = hfma3(pairsum(acc[4], acc[5]), 0xC000C000u, f2h);
        unsigned pk3 = hfma3(pairsum(acc[6], acc[7]), 0xC000C000u, f2h);

        // ---- two-phase reduction (20 SHFL total)
        // phase 1: offsets 16, 8 on all 5 values -> residue (mod 8) partials
#pragma unroll
        for (int off = 16; off >= 8; off >>= 1) {
            pk0 = hadd2(pk0, __shfl_xor_sync(0xffffffffu, pk0, off));
            pk1 = hadd2(pk1, __shfl_xor_sync(0xffffffffu, pk1, off));
            pk2 = hadd2(pk2, __shfl_xor_sync(0xffffffffu, pk2, off));
            pk3 = hadd2(pk3, __shfl_xor_sync(0xffffffffu, pk3, off));
            pos_t += __shfl_xor_sync(0xffffffffu, pos_t, off);
        }
        // phase 2: each 8-lane group finishes one packed value
        const int g = lane >> 3;
        unsigned v = (g == 0) ? pk0 : (g == 1) ? pk1 : (g == 2) ? pk2 : pk3;
#pragma unroll
        for (int off = 4; off > 0; off >>= 1) {
            v = hadd2(v, __shfl_xor_sync(0xffffffffu, v, off));
            pos_t += __shfl_xor_sync(0xffffffffu, pos_t, off);
        }
        // gather: lane k takes pk[k>>1] full sum from lane 8*(k>>1)
        unsigned pv = __shfl_sync(0xffffffffu, v, (lane >> 1) << 3);

        // lane-parallel guard: lane k<8 checks neg k's subset d2 lower bound
        const int k = lane;
        __half2 hv = *reinterpret_cast<__half2*>(&pv);
        float tneg = (k & 1) ? __half2float(hv.y) : __half2float(hv.x);
        int nidx = (k == 0) ? nv0 : (k == 1) ? nv1 : (k == 2) ? nv2 :
                   (k == 3) ? nv3 : (k == 4) ? nv4 : (k == 5) ? nv5 :
                   (k == 6) ? nv6 : nv7;
        float d2sub = tneg + sA2n[nidx];
        bool okk = (k < 8) ? (d2sub >= D2SUB_GUARD) : true;
        bool fast = (__ballot_sync(0xffffffffu, okk) == 0xffffffffu);

        float nl = 0.f;
        if (!fast) {
            // exact fp32 fallback (statistically never taken; unconditional
            // correctness). NOTE: f0..f3 now hold the NEXT point's features,
            // so reload this point's features here.
            const float4* f4c = reinterpret_cast<const float4*>(feats + (size_t)p * DIM);
            float4 c0 = f4c[lane], c1 = f4c[lane + 32],
                   c2 = f4c[lane + 64], c3 = f4c[lane + 96];
            float nsum = 0.f;
            for (int kk = 0; kk < 8; kk++) {
                int idx = aidx[kk];
                const float4* ap = reinterpret_cast<const float4*>(anchors + idx * DIM);
                float4 a0 = ap[lane], a1 = ap[lane + 32],
                       a2 = ap[lane + 64], a3 = ap[lane + 96];
                float t = 0.f;
                t = fmaf(c0.x - a0.x, c0.x - a0.x, t);
                t = fmaf(c0.y - a0.y, c0.y - a0.y, t);
                t = fmaf(c0.z - a0.z, c0.z - a0.z, t);
                t = fmaf(c0.w - a0.w, c0.w - a0.w, t);
                t = fmaf(c1.x - a1.x, c1.x - a1.x, t);
                t = fmaf(c1.y - a1.y, c1.y - a1.y, t);
                t = fmaf(c1.z - a1.z, c1.z - a1.z, t);
                t = fmaf(c1.w - a1.w, c1.w - a1.w, t);
                t = fmaf(c2.x - a2.x, c2.x - a2.x, t);
                t = fmaf(c2.y - a2.y, c2.y - a2.y, t);
                t = fmaf(c2.z - a2.z, c2.z - a2.z, t);
                t = fmaf(c2.w - a2.w, c2.w - a2.w, t);
                t = fmaf(c3.x - a3.x, c3.x - a3.x, t);
                t = fmaf(c3.y - a3.y, c3.y - a3.y, t);
                t = fmaf(c3.z - a3.z, c3.z - a3.z, t);
                t = fmaf(c3.w - a3.w, c3.w - a3.w, t);
                float d2 = wred(t);
                nsum += sqrtf(fmaxf(d2, 0.f) + EPSF);
            }
            nl = fmaxf(NEG_TH - nsum * 0.125f, 0.f);
        }

        if (lane == 0) {
            float d2pv = pos_t + sA2p[lblc];
            float distp = sqrt_approx(fmaxf(d2pv, 0.f) + EPSF);
            bool  valid = (lbl != IGNORE_LBL);
            float pl = valid ? fmaxf(distp, 0.f) : 0.f;        // POS_THRESH=0
            float nlv = valid ? nl : 0.f;
            if (writeArrays) {
                out[1 + p]        = pl;
                out[1 + NPTS + p] = nlv;
            }
            sumPos += pl;
            sumNeg += nlv;
        }

        p = pn;
    }

    // ---- block partials
    if (lane == 0) {
        sRed[warpId]          = sumPos;
        sRed[NWARPS + warpId] = sumNeg;
    }
    __syncthreads();
    if (threadIdx.x < 32) {
        float sp = (threadIdx.x < NWARPS) ? sRed[threadIdx.x] : 0.f;
        float sn = (threadIdx.x < NWARPS) ? sRed[NWARPS + threadIdx.x] : 0.f;
        sp = wred(sp);
        sn = wred(sn);
        if (threadIdx.x == 0) {
            g_ppos[blockIdx.x] = sp;
            g_pneg[blockIdx.x] = sn;
        }
    }

    // ---- last-block grid reduction
    if (threadIdx.x == 0) {
        __threadfence();
        unsigned int c = atomicAdd(&g_count, 1u);
        sIsLast = (c == (unsigned)(BLOCKS - 1)) ? 1 : 0;
    }
    __syncthreads();
    if (sIsLast) {
        __threadfence();
        float sp = 0.f, sn = 0.f;
        if (threadIdx.x < BLOCKS) {
            sp = g_ppos[threadIdx.x];
            sn = g_pneg[threadIdx.x];
        }
        if (warpId < 5) {
            sp = wred(sp);
            sn = wred(sn);
            if (lane == 0) { sRed[warpId] = sp; sRed[8 + warpId] = sn; }
        }
        __syncthreads();
        if (threadIdx.x == 0) {
            float tp = 0.f, tn = 0.f;
#pragma unroll
            for (int i = 0; i < 5; i++) { tp += sRed[i]; tn += sRed[8 + i]; }
            out[0] = (tp + tn) * (1.0f / (float)NPTS);
            atomicExch(&g_count, 0u);      // reset for next graph replay
        }
    }
}

extern "C" void kernel_launch(void* const* d_in, const int* in_sizes, int n_in,
                              void* d_out, int out_size) {
    const float* feats   = (const float*)d_in[0];
    const void*  labels  = d_in[1];
    const float* anchors = (const float*)d_in[2];
    const void*  negs    = d_in[3];
    float* out = (float*)d_out;

    const int writeArrays = (out_size >= 1 + 2 * NPTS) ? 1 : 0;

    cudaFuncSetAttribute(loss_kernel, cudaFuncAttributeMaxDynamicSharedMemorySize, SMEM_BYTES);
    loss_kernel<<<BLOCKS, NTHREADS, SMEM_BYTES>>>(feats, labels, anchors, negs, out, writeArrays);
}

// round 8
// speedup vs baseline: 2.1186x; 1.1505x over previous
#include <cuda_runtime.h>
#include <cuda_fp16.h>
#include <stdint.h>

#define NPTS 262144
#define DIM 512
#define NLBL 200
#define KNEG 8
#define EPSF 1e-7f
#define NEG_TH 0.85f
#define IGNORE_LBL 255
#define D2SUB_GUARD 64.0f   // true d2_sub >= computed - 60 ; >=64 => dist >= 2 > 0.85

constexpr int BLOCKS   = 152;
constexpr int NTHREADS = 1024;           // 32 warps/SM @ 64 regs
constexpr int NWARPS   = NTHREADS / 32;
constexpr int TOTWARPS = BLOCKS * NWARPS;

// dynamic smem: compact e5m2 subset table (128B/row) + a2 tables + scratch
constexpr int SM_SUB_BYTES = NLBL * 128;            // 25600 B
constexpr int SM_A2P_OFF   = SM_SUB_BYTES;
constexpr int SM_A2N_OFF   = SM_A2P_OFF + 1024;
constexpr int SM_RED_OFF   = SM_A2N_OFF + 1024;
constexpr int SMEM_BYTES   = SM_RED_OFF + 2 * NWARPS * 4;

// fp16 positive-anchor table in gmem (L1-cached; features use streaming loads)
__device__ uint4 g_posU4[NLBL * 64];

__device__ float g_ppos[BLOCKS];
__device__ float g_pneg[BLOCKS];
__device__ unsigned int g_count = 0;

// ---------------------------------------------------------------------------
// helpers
// ---------------------------------------------------------------------------
__device__ __forceinline__ unsigned cvt_f16x2(float hi, float lo) {
    unsigned r;
    asm("cvt.rn.f16x2.f32 %0, %1, %2;" : "=r"(r) : "f"(hi), "f"(lo));
    return r;
}
__device__ __forceinline__ void hfma2(unsigned& acc, unsigned a, unsigned b) {
    asm("fma.rn.f16x2 %0, %1, %2, %0;" : "+r"(acc) : "r"(a), "r"(b));
}
__device__ __forceinline__ unsigned hfma3(unsigned a, unsigned b, unsigned c) {
    unsigned r;
    asm("fma.rn.f16x2 %0, %1, %2, %3;" : "=r"(r) : "r"(a), "r"(b), "r"(c));
    return r;
}
__device__ __forceinline__ unsigned hadd2(unsigned a, unsigned b) {
    unsigned r;
    asm("add.rn.f16x2 %0, %1, %2;" : "=r"(r) : "r"(a), "r"(b));
    return r;
}
__device__ __forceinline__ unsigned prmt(unsigned a, unsigned b, unsigned sel) {
    unsigned r;
    asm("prmt.b32 %0, %1, %2, %3;" : "=r"(r) : "r"(a), "r"(b), "r"(sel));
    return r;
}
__device__ __forceinline__ unsigned prmt0(unsigned a, unsigned sel) {
    unsigned r;
    asm("prmt.b32 %0, %1, %2, %3;" : "=r"(r) : "r"(a), "r"(0u), "r"(sel));
    return r;
}
__device__ __forceinline__ unsigned pairsum(unsigned a, unsigned b) {
    return hadd2(prmt(a, b, 0x5410u), prmt(a, b, 0x7632u));
}
__device__ __forceinline__ float sqrt_approx(float x) {
    float r;
    asm("sqrt.approx.f32 %0, %1;" : "=f"(r) : "f"(x));
    return r;
}
__device__ __forceinline__ float wred(float v) {
#pragma unroll
    for (int off = 16; off > 0; off >>= 1)
        v += __shfl_xor_sync(0xffffffffu, v, off);
    return v;
}
__device__ __forceinline__ float4 ldcs4(const float4* p) {
    float4 v;
    asm("ld.global.cs.v4.f32 {%0,%1,%2,%3}, [%4];"
        : "=f"(v.x), "=f"(v.y), "=f"(v.z), "=f"(v.w) : "l"(p));
    return v;
}

// ---------------------------------------------------------------------------
// Cold exact fp32 fallback (statistically never taken; keeps the bound-based
// zero unconditional). __noinline__ so its registers don't inflate the hot
// path allocation.
// ---------------------------------------------------------------------------
__device__ __noinline__ float neg_fallback(const float* __restrict__ feats,
                                           const float* __restrict__ anchors,
                                           const void*  __restrict__ negs_v,
                                           int n64flag, int p, int lane) {
    const float4* f4c = reinterpret_cast<const float4*>(feats + (size_t)p * DIM);
    float4 c0 = f4c[lane], c1 = f4c[lane + 32],
           c2 = f4c[lane + 64], c3 = f4c[lane + 96];
    float nsum = 0.f;
    for (int kk = 0; kk < 8; kk++) {
        int idx;
        if (n64flag)
            idx = (int)reinterpret_cast<const long long*>(negs_v)[(size_t)p * KNEG + kk];
        else
            idx = reinterpret_cast<const int*>(negs_v)[(size_t)p * KNEG + kk];
        idx = min(idx, NLBL - 1);
        const float4* ap = reinterpret_cast<const float4*>(anchors + idx * DIM);
        float4 a0 = ap[lane], a1 = ap[lane + 32],
               a2 = ap[lane + 64], a3 = ap[lane + 96];
        float t = 0.f;
        t = fmaf(c0.x - a0.x, c0.x - a0.x, t);
        t = fmaf(c0.y - a0.y, c0.y - a0.y, t);
        t = fmaf(c0.z - a0.z, c0.z - a0.z, t);
        t = fmaf(c0.w - a0.w, c0.w - a0.w, t);
        t = fmaf(c1.x - a1.x, c1.x - a1.x, t);
        t = fmaf(c1.y - a1.y, c1.y - a1.y, t);
        t = fmaf(c1.z - a1.z, c1.z - a1.z, t);
        t = fmaf(c1.w - a1.w, c1.w - a1.w, t);
        t = fmaf(c2.x - a2.x, c2.x - a2.x, t);
        t = fmaf(c2.y - a2.y, c2.y - a2.y, t);
        t = fmaf(c2.z - a2.z, c2.z - a2.z, t);
        t = fmaf(c2.w - a2.w, c2.w - a2.w, t);
        t = fmaf(c3.x - a3.x, c3.x - a3.x, t);
        t = fmaf(c3.y - a3.y, c3.y - a3.y, t);
        t = fmaf(c3.z - a3.z, c3.z - a3.z, t);
        t = fmaf(c3.w - a3.w, c3.w - a3.w, t);
        float d2 = wred(t);
        nsum += sqrtf(fmaxf(d2, 0.f) + EPSF);
    }
    return fmaxf(NEG_TH - nsum * 0.125f, 0.f);
}

// ---------------------------------------------------------------------------
// Single fused kernel.
// ---------------------------------------------------------------------------
__global__ __launch_bounds__(NTHREADS, 1)
void loss_kernel(const float* __restrict__ feats,
                 const void*  __restrict__ labels_v,
                 const float* __restrict__ anchors,
                 const void*  __restrict__ negs_v,
                 float* __restrict__ out,
                 int writeArrays) {
    extern __shared__ unsigned char smem[];
    unsigned* sSub = reinterpret_cast<unsigned*>(smem);
    float* sA2p = reinterpret_cast<float*>(smem + SM_A2P_OFF);
    float* sA2n = reinterpret_cast<float*>(smem + SM_A2N_OFF);
    float* sRed = reinterpret_cast<float*>(smem + SM_RED_OFF);
    __shared__ int sFlags;
    __shared__ int sIsLast;

    const int warpId = threadIdx.x >> 5;
    const int lane   = threadIdx.x & 31;

    // ---- dtype sniff: values nonneg < 200 -> odd int32 words zero iff int64
    if (warpId == 0) {
        const int* li = reinterpret_cast<const int*>(labels_v);
        const int* ni = reinterpret_cast<const int*>(negs_v);
        int lnz = li[2 * lane + 1] | li[2 * lane + 65];
        int nnz = ni[2 * lane + 1] | ni[2 * lane + 65];
        unsigned lb = __ballot_sync(0xffffffffu, lnz != 0);
        unsigned nb = __ballot_sync(0xffffffffu, nnz != 0);
        if (lane == 0) sFlags = ((lb == 0u) ? 1 : 0) | ((nb == 0u) ? 2 : 0);
    }

    // ---- stage anchors: fp16 pos table (gmem) + e5m2 subset table (smem) + a2s
    for (int r = warpId; r < NLBL; r += NWARPS) {
        const float4* src = reinterpret_cast<const float4*>(anchors + r * DIM);
        unsigned w[8];
        float a2p = 0.f;
#pragma unroll
        for (int c = 0; c < 4; c++) {
            float4 v = src[lane + 32 * c];
            w[2 * c]     = cvt_f16x2(v.y, v.x);
            w[2 * c + 1] = cvt_f16x2(v.w, v.z);
        }
#pragma unroll
        for (int j = 0; j < 8; j++) {
            __half2 h = *reinterpret_cast<__half2*>(&w[j]);
            float2 q = __half22float2(h);
            a2p = fmaf(q.x, q.x, a2p);
            a2p = fmaf(q.y, q.y, a2p);
        }
        unsigned w0r = w[0] + 0x0080u;
        unsigned w2r = w[2] + 0x0080u;
        unsigned w4r = w[4] + 0x0080u;
        unsigned w6r = w[6] + 0x0080u;
        unsigned x01 = prmt(w0r, w2r, 0x0051u);
        unsigned x23 = prmt(w4r, w6r, 0x0051u);
        unsigned subw = prmt(x01, x23, 0x5410u);
        unsigned plo = prmt0(subw, 0x1404u);
        unsigned phi = prmt0(subw, 0x3424u);
        __half2 hlo = *reinterpret_cast<__half2*>(&plo);
        __half2 hhi = *reinterpret_cast<__half2*>(&phi);
        float2 qlo = __half22float2(hlo);
        float2 qhi = __half22float2(hhi);
        float a2n = qlo.x * qlo.x;
        a2n = fmaf(qlo.y, qlo.y, a2n);
        a2n = fmaf(qhi.x, qhi.x, a2n);
        a2n = fmaf(qhi.y, qhi.y, a2n);

        sSub[r * 32 + lane] = subw;
        g_posU4[r * 64 + lane]      = make_uint4(w[0], w[1], w[2], w[3]);
        g_posU4[r * 64 + 32 + lane] = make_uint4(w[4], w[5], w[6], w[7]);
        float s2p = wred(a2p);
        float s2n = wred(a2n);
        if (lane == 0) { sA2p[r] = s2p; sA2n[r] = s2n; }
    }
    __syncthreads();

    const int l64 = (sFlags & 1);
    const int n64 = (sFlags & 2);

    float sumPos = 0.f, sumNeg = 0.f;

    int p = blockIdx.x * NWARPS + warpId;
    float4 f0, f1, f2v, f3;
    if (p < NPTS) {
        const float4* f4 = reinterpret_cast<const float4*>(feats + (size_t)p * DIM);
        f0  = ldcs4(f4 + lane);
        f1  = ldcs4(f4 + lane + 32);
        f2v = ldcs4(f4 + lane + 64);
        f3  = ldcs4(f4 + lane + 96);
    }

    for (; p < NPTS; ) {
        const int pn = p + TOTWARPS;

        // indices for current point (broadcast loads)
        int lbl = l64 ? (int)reinterpret_cast<const long long*>(labels_v)[p]
                      : reinterpret_cast<const int*>(labels_v)[p];
        int aidx[8];
        if (n64) {
            const uint4* np = reinterpret_cast<const uint4*>(
                (const char*)negs_v + (size_t)p * 64);
            uint4 a = np[0], b = np[1], c = np[2], d = np[3];
            aidx[0] = (int)a.x; aidx[1] = (int)a.z;
            aidx[2] = (int)b.x; aidx[3] = (int)b.z;
            aidx[4] = (int)c.x; aidx[5] = (int)c.z;
            aidx[6] = (int)d.x; aidx[7] = (int)d.z;
        } else {
            const uint4* np = reinterpret_cast<const uint4*>(
                (const char*)negs_v + (size_t)p * 32);
            uint4 a = np[0], b = np[1];
            aidx[0] = (int)a.x; aidx[1] = (int)a.y; aidx[2] = (int)a.z; aidx[3] = (int)a.w;
            aidx[4] = (int)b.x; aidx[5] = (int)b.y; aidx[6] = (int)b.z; aidx[7] = (int)b.w;
        }
#pragma unroll
        for (int k = 0; k < 8; k++) aidx[k] = min(aidx[k], NLBL - 1);
        const int lblc = min(lbl, NLBL - 1);

        // positive anchor fp16 (L1-resident; features bypass L1 via ldcs)
        const uint4* pp = &g_posU4[lblc * 64];
        uint4 pa = pp[lane];
        uint4 pb = pp[lane + 32];

        // ||f||^2 + subset partial + f16 conversion (consumes fp32 features)
        float f2p = f0.x * f0.x;
        f2p = fmaf(f0.y, f0.y, f2p); f2p = fmaf(f0.z, f0.z, f2p); f2p = fmaf(f0.w, f0.w, f2p);
        f2p = fmaf(f1.x, f1.x, f2p); f2p = fmaf(f1.y, f1.y, f2p); f2p = fmaf(f1.z, f1.z, f2p); f2p = fmaf(f1.w, f1.w, f2p);
        f2p = fmaf(f2v.x, f2v.x, f2p); f2p = fmaf(f2v.y, f2v.y, f2p); f2p = fmaf(f2v.z, f2v.z, f2p); f2p = fmaf(f2v.w, f2v.w, f2p);
        f2p = fmaf(f3.x, f3.x, f2p); f2p = fmaf(f3.y, f3.y, f2p); f2p = fmaf(f3.z, f3.z, f2p); f2p = fmaf(f3.w, f3.w, f2p);
        float f2s = f0.x * f0.x;
        f2s = fmaf(f1.x, f1.x, f2s);
        f2s = fmaf(f2v.x, f2v.x, f2s);
        f2s = fmaf(f3.x, f3.x, f2s);

        unsigned fh[8];
        fh[0] = cvt_f16x2(f0.y, f0.x);   fh[1] = cvt_f16x2(f0.w, f0.z);
        fh[2] = cvt_f16x2(f1.y, f1.x);   fh[3] = cvt_f16x2(f1.w, f1.z);
        fh[4] = cvt_f16x2(f2v.y, f2v.x); fh[5] = cvt_f16x2(f2v.w, f2v.z);
        fh[6] = cvt_f16x2(f3.y, f3.x);   fh[7] = cvt_f16x2(f3.w, f3.z);
        unsigned fs0 = prmt(fh[0], fh[2], 0x5410u);
        unsigned fs1 = prmt(fh[4], fh[6], 0x5410u);

        // ---- PREFETCH next point's features (fp32 regs now dead)
        if (pn < NPTS) {
            const float4* f4n = reinterpret_cast<const float4*>(feats + (size_t)pn * DIM);
            f0  = ldcs4(f4n + lane);
            f1  = ldcs4(f4n + lane + 32);
            f2v = ldcs4(f4n + lane + 64);
            f3  = ldcs4(f4n + lane + 96);
        }

        // positive dot: 8 HFMA2
        unsigned pacc = 0u;
        hfma2(pacc, pa.x, fh[0]); hfma2(pacc, pa.y, fh[1]);
        hfma2(pacc, pa.z, fh[2]); hfma2(pacc, pa.w, fh[3]);
        hfma2(pacc, pb.x, fh[4]); hfma2(pacc, pb.y, fh[5]);
        hfma2(pacc, pb.z, fh[6]); hfma2(pacc, pb.w, fh[7]);
        __half2 ph = *reinterpret_cast<__half2*>(&pacc);
        float2 pf = __half22float2(ph);
        float pos_t = fmaf(-2.f, pf.x + pf.y, f2p);

        // 8 negative subset dots, pairsummed incrementally (low live state)
        unsigned f2h = cvt_f16x2(f2s, f2s);
        unsigned pk0, pk1, pk2, pk3;
        {
            unsigned qa, qb, da, db;
            qa = sSub[aidx[0] * 32 + lane]; qb = sSub[aidx[1] * 32 + lane];
            da = 0u; hfma2(da, prmt0(qa, 0x1404u), fs0); hfma2(da, prmt0(qa, 0x3424u), fs1);
            db = 0u; hfma2(db, prmt0(qb, 0x1404u), fs0); hfma2(db, prmt0(qb, 0x3424u), fs1);
            pk0 = hfma3(pairsum(da, db), 0xC000C000u, f2h);
            qa = sSub[aidx[2] * 32 + lane]; qb = sSub[aidx[3] * 32 + lane];
            da = 0u; hfma2(da, prmt0(qa, 0x1404u), fs0); hfma2(da, prmt0(qa, 0x3424u), fs1);
            db = 0u; hfma2(db, prmt0(qb, 0x1404u), fs0); hfma2(db, prmt0(qb, 0x3424u), fs1);
            pk1 = hfma3(pairsum(da, db), 0xC000C000u, f2h);
            qa = sSub[aidx[4] * 32 + lane]; qb = sSub[aidx[5] * 32 + lane];
            da = 0u; hfma2(da, prmt0(qa, 0x1404u), fs0); hfma2(da, prmt0(qa, 0x3424u), fs1);
            db = 0u; hfma2(db, prmt0(qb, 0x1404u), fs0); hfma2(db, prmt0(qb, 0x3424u), fs1);
            pk2 = hfma3(pairsum(da, db), 0xC000C000u, f2h);
            qa = sSub[aidx[6] * 32 + lane]; qb = sSub[aidx[7] * 32 + lane];
            da = 0u; hfma2(da, prmt0(qa, 0x1404u), fs0); hfma2(da, prmt0(qa, 0x3424u), fs1);
            db = 0u; hfma2(db, prmt0(qb, 0x1404u), fs0); hfma2(db, prmt0(qb, 0x3424u), fs1);
            pk3 = hfma3(pairsum(da, db), 0xC000C000u, f2h);
        }

        // ---- two-phase reduction (20 SHFL total)
#pragma unroll
        for (int off = 16; off >= 8; off >>= 1) {
            pk0 = hadd2(pk0, __shfl_xor_sync(0xffffffffu, pk0, off));
            pk1 = hadd2(pk1, __shfl_xor_sync(0xffffffffu, pk1, off));
            pk2 = hadd2(pk2, __shfl_xor_sync(0xffffffffu, pk2, off));
            pk3 = hadd2(pk3, __shfl_xor_sync(0xffffffffu, pk3, off));
            pos_t += __shfl_xor_sync(0xffffffffu, pos_t, off);
        }
        const int g = lane >> 3;
        unsigned v = (g == 0) ? pk0 : (g == 1) ? pk1 : (g == 2) ? pk2 : pk3;
#pragma unroll
        for (int off = 4; off > 0; off >>= 1) {
            v = hadd2(v, __shfl_xor_sync(0xffffffffu, v, off));
            pos_t += __shfl_xor_sync(0xffffffffu, pos_t, off);
        }
        unsigned pv = __shfl_sync(0xffffffffu, v, (lane >> 1) << 3);

        // lane-parallel guard: lane k<8 checks neg k's subset d2 lower bound
        const int k = lane;
        __half2 hv = *reinterpret_cast<__half2*>(&pv);
        float tneg = (k & 1) ? __half2float(hv.y) : __half2float(hv.x);
        // per-lane index reload (L1 hit) instead of 7-deep select chain
        int nidx;
        {
            int kk = k & 7;
            if (n64) nidx = (int)reinterpret_cast<const long long*>(negs_v)[(size_t)p * KNEG + kk];
            else     nidx = reinterpret_cast<const int*>(negs_v)[(size_t)p * KNEG + kk];
            nidx = min(nidx, NLBL - 1);
        }
        float d2sub = tneg + sA2n[nidx];
        bool okk = (k < 8) ? (d2sub >= D2SUB_GUARD) : true;
        bool fast = (__ballot_sync(0xffffffffu, okk) == 0xffffffffu);

        float nl = 0.f;
        if (!fast) nl = neg_fallback(feats, anchors, negs_v, n64, p, lane);

        if (lane == 0) {
            float d2pv = pos_t + sA2p[lblc];
            float distp = sqrt_approx(fmaxf(d2pv, 0.f) + EPSF);
            bool  valid = (lbl != IGNORE_LBL);
            float pl = valid ? fmaxf(distp, 0.f) : 0.f;        // POS_THRESH=0
            float nlv = valid ? nl : 0.f;
            if (writeArrays) {
                out[1 + p]        = pl;
                out[1 + NPTS + p] = nlv;
            }
            sumPos += pl;
            sumNeg += nlv;
        }

        p = pn;
    }

    // ---- block partials
    if (lane == 0) {
        sRed[warpId]          = sumPos;
        sRed[NWARPS + warpId] = sumNeg;
    }
    __syncthreads();
    if (threadIdx.x < 32) {
        float sp = (threadIdx.x < NWARPS) ? sRed[threadIdx.x] : 0.f;
        float sn = (threadIdx.x < NWARPS) ? sRed[NWARPS + threadIdx.x] : 0.f;
        sp = wred(sp);
        sn = wred(sn);
        if (threadIdx.x == 0) {
            g_ppos[blockIdx.x] = sp;
            g_pneg[blockIdx.x] = sn;
        }
    }

    // ---- last-block grid reduction
    if (threadIdx.x == 0) {
        __threadfence();
        unsigned int c = atomicAdd(&g_count, 1u);
        sIsLast = (c == (unsigned)(BLOCKS - 1)) ? 1 : 0;
    }
    __syncthreads();
    if (sIsLast) {
        __threadfence();
        float sp = 0.f, sn = 0.f;
        if (threadIdx.x < BLOCKS) {
            sp = g_ppos[threadIdx.x];
            sn = g_pneg[threadIdx.x];
        }
        if (warpId < 5) {
            sp = wred(sp);
            sn = wred(sn);
            if (lane == 0) { sRed[warpId] = sp; sRed[8 + warpId] = sn; }
        }
        __syncthreads();
        if (threadIdx.x == 0) {
            float tp = 0.f, tn = 0.f;
#pragma unroll
            for (int i = 0; i < 5; i++) { tp += sRed[i]; tn += sRed[8 + i]; }
            out[0] = (tp + tn) * (1.0f / (float)NPTS);
            atomicExch(&g_count, 0u);      // reset for next graph replay
        }
    }
}

extern "C" void kernel_launch(void* const* d_in, const int* in_sizes, int n_in,
                              void* d_out, int out_size) {
    const float* feats   = (const float*)d_in[0];
    const void*  labels  = d_in[1];
    const float* anchors = (const float*)d_in[2];
    const void*  negs    = d_in[3];
    float* out = (float*)d_out;

    const int writeArrays = (out_size >= 1 + 2 * NPTS) ? 1 : 0;

    cudaFuncSetAttribute(loss_kernel, cudaFuncAttributeMaxDynamicSharedMemorySize, SMEM_BYTES);
    loss_kernel<<<BLOCKS, NTHREADS, SMEM_BYTES>>>(feats, labels, anchors, negs, out, writeArrays);
}